// round 12
// baseline (speedup 1.0000x reference)
#include <cuda_runtime.h>
#include <cuda_bf16.h>
#include <math.h>
#include <stdint.h>

// ---------------------------------------------------------------------------
// GCN_Protein: 3x GCNConv -> mean pool -> MLP -> log_softmax
//   R11: tcgen05 is sm_103a-only and the harness builds for compute_103 ->
//        pivot GEMMs to warp-level mma.sync bf16 (PTX-portable HMMA).
//        Split precision via K-expansion: A'=[hi,hi,lo], B'=[hi,lo,hi] per
//        original k => C = hiA*hiB + hiA*loB + loA*hiB (err ~2^-17).
//   SpMM / CSR build / pool / cls unchanged from the 436us kernel.
// ---------------------------------------------------------------------------

#define NN 100000
#define NE 1600000
#define NTOT (NN + NE)
#define NG 512
#define OUTF 10

#define SCAN_B 512
#define SCAN_NB ((NN + SCAN_B - 1) / SCAN_B)   // 196

// ------------------------- scratch (device globals) ------------------------
__device__ int   g_e64;
__device__ int   g_b64;
__device__ int   g_deg[NN];
__device__ int   g_rowptr[NN + 1];
__device__ int   g_cursor[NN];
__device__ float g_dinv[NN];
__device__ int   g_part[SCAN_NB];
__device__ int   g_partoff[SCAN_NB];
__device__ int2  g_colw[NTOT];               // packed {col, float_as_int(wgt)}
__device__ float g_bufA[(size_t)NN * 64];
__device__ float g_bufB[(size_t)NN * 64];
__device__ float g_bufC[(size_t)NN * 128];
__device__ float g_bufD[(size_t)NN * 128];
__device__ float g_pool[NG * 128];
__device__ float g_cnt[NG];

template <int ID>
__device__ __forceinline__ float* scratch() {
    if (ID == 0) return g_bufA;
    if (ID == 1) return g_bufB;
    if (ID == 2) return g_bufC;
    return g_bufD;
}

__device__ __forceinline__ int clampi(int v, int hi) {
    return v < 0 ? 0 : (v >= hi ? hi - 1 : v);
}

__device__ __forceinline__ int load_idx(const int* __restrict__ p, int i, int is64) {
    return is64 ? p[2 * i] : p[i];
}

// ------------------------------ mma.sync helper ------------------------------
__device__ __forceinline__ void mma_16816(float* c, const uint32_t* a,
                                          uint32_t b0, uint32_t b1) {
    asm volatile(
        "mma.sync.aligned.m16n8k16.row.col.f32.bf16.bf16.f32 "
        "{%0,%1,%2,%3}, {%4,%5,%6,%7}, {%8,%9}, {%0,%1,%2,%3};"
        : "+f"(c[0]), "+f"(c[1]), "+f"(c[2]), "+f"(c[3])
        : "r"(a[0]), "r"(a[1]), "r"(a[2]), "r"(a[3]), "r"(b0), "r"(b1));
}

// ------------------------------ dtype detection ------------------------------
__global__ void k_detect(const int* __restrict__ ei, const int* __restrict__ batch) {
    __shared__ int nz_e, nz_b;
    int t = threadIdx.x;                       // 128 threads
    if (t == 0) { nz_e = 0; nz_b = 0; }
    __syncthreads();
    long long stride = (2LL * NE) / 128;
    int we = (int)((long long)t * stride) | 1;
    if (ei[we] != 0) atomicAdd(&nz_e, 1);
    int wb = (NN - 1 - 2 * t) | 1;
    if (batch[wb] != 0) atomicAdd(&nz_b, 1);
    __syncthreads();
    if (t == 0) { g_e64 = (nz_e == 0); g_b64 = (nz_b == 0); }
}

// ------------------------------ preprocessing ------------------------------
__global__ void k_init() {
    int i = blockIdx.x * blockDim.x + threadIdx.x;
    if (i < NN) { g_deg[i] = 1; g_cursor[i] = 0; }   // self-loop contributes 1
    if (i < NG * 128) g_pool[i] = 0.f;
    if (i < NG) g_cnt[i] = 0.f;
}

__global__ void k_count(const int* __restrict__ ei) {
    int e = blockIdx.x * blockDim.x + threadIdx.x;
    if (e < NE) {
        int d = clampi(load_idx(ei, NE + e, g_e64), NN);
        atomicAdd(&g_deg[d], 1);
    }
}

__global__ void k_part() {
    __shared__ int red[SCAN_B];
    int t = threadIdx.x;
    int i = blockIdx.x * SCAN_B + t;
    red[t] = (i < NN) ? g_deg[i] : 0;
    __syncthreads();
#pragma unroll
    for (int off = SCAN_B / 2; off > 0; off >>= 1) {
        if (t < off) red[t] += red[t + off];
        __syncthreads();
    }
    if (t == 0) g_part[blockIdx.x] = red[0];
}

__global__ void k_scanpart() {
    __shared__ int s[256];
    int t = threadIdx.x;
    int v = (t < SCAN_NB) ? g_part[t] : 0;
    s[t] = v;
    __syncthreads();
#pragma unroll
    for (int off = 1; off < 256; off <<= 1) {
        int x = (t >= off) ? s[t - off] : 0;
        __syncthreads();
        s[t] += x;
        __syncthreads();
    }
    if (t < SCAN_NB) g_partoff[t] = s[t] - v;  // exclusive
}

__global__ void k_write() {
    __shared__ int s[SCAN_B];
    int t = threadIdx.x;
    int i = blockIdx.x * SCAN_B + t;
    int v = (i < NN) ? g_deg[i] : 0;
    s[t] = v;
    __syncthreads();
#pragma unroll
    for (int off = 1; off < SCAN_B; off <<= 1) {
        int x = (t >= off) ? s[t - off] : 0;
        __syncthreads();
        s[t] += x;
        __syncthreads();
    }
    int base = g_partoff[blockIdx.x];
    if (i < NN) {
        g_rowptr[i] = base + s[t] - v;         // exclusive
        g_dinv[i]   = rsqrtf((float)v);
    }
    if (i == NN - 1) g_rowptr[NN] = base + s[t];
}

__global__ void k_fill(const int* __restrict__ ei) {
    int idx = blockIdx.x * blockDim.x + threadIdx.x;
    if (idx < NN) {
        int pos = g_rowptr[idx] + atomicAdd(&g_cursor[idx], 1);
        float di = g_dinv[idx];
        g_colw[pos] = make_int2(idx, __float_as_int(di * di));
    } else if (idx < NTOT) {
        int e = idx - NN;
        int is64 = g_e64;
        int s = clampi(load_idx(ei, e, is64), NN);
        int d = clampi(load_idx(ei, NE + e, is64), NN);
        int pos = g_rowptr[d] + atomicAdd(&g_cursor[d], 1);
        g_colw[pos] = make_int2(s, __float_as_int(g_dinv[s] * g_dinv[d]));
    }
}

// ---------------------------------- SpMM -----------------------------------
template <int F, bool EPI, int IN, int OUT>
__global__ void k_spmm(const float* __restrict__ bias) {
    const float* __restrict__ hin  = scratch<IN>();
    float*       __restrict__ hout = scratch<OUT>();
    constexpr int VEC = F / 32;
    int warp = (blockIdx.x * blockDim.x + threadIdx.x) >> 5;
    int lane = threadIdx.x & 31;
    if (warp >= NN) return;
    int beg = g_rowptr[warp], end = g_rowptr[warp + 1];
    float acc[VEC];
#pragma unroll
    for (int v = 0; v < VEC; v++) acc[v] = 0.f;

    int k = beg;
    for (; k + 2 <= end; k += 2) {
        int2 e0 = g_colw[k];
        int2 e1 = g_colw[k + 1];
        float w0 = __int_as_float(e0.y);
        float w1 = __int_as_float(e1.y);
        const float* p0 = hin + (size_t)e0.x * F + lane * VEC;
        const float* p1 = hin + (size_t)e1.x * F + lane * VEC;
        if (VEC == 4) {
            float4 v0 = *(const float4*)p0;
            float4 v1 = *(const float4*)p1;
            acc[0] += w0 * v0.x; acc[1] += w0 * v0.y;
            acc[2] += w0 * v0.z; acc[3] += w0 * v0.w;
            acc[0] += w1 * v1.x; acc[1] += w1 * v1.y;
            acc[2] += w1 * v1.z; acc[3] += w1 * v1.w;
        } else {
            float2 v0 = *(const float2*)p0;
            float2 v1 = *(const float2*)p1;
            acc[0] += w0 * v0.x; acc[1] += w0 * v0.y;
            acc[0] += w1 * v1.x; acc[1] += w1 * v1.y;
        }
    }
    if (k < end) {
        int2 e0 = g_colw[k];
        float w0 = __int_as_float(e0.y);
        const float* p0 = hin + (size_t)e0.x * F + lane * VEC;
        if (VEC == 4) {
            float4 v0 = *(const float4*)p0;
            acc[0] += w0 * v0.x; acc[1] += w0 * v0.y;
            acc[2] += w0 * v0.z; acc[3] += w0 * v0.w;
        } else {
            float2 v0 = *(const float2*)p0;
            acc[0] += w0 * v0.x; acc[1] += w0 * v0.y;
        }
    }

    float* q = hout + (size_t)warp * F + lane * VEC;
    if (EPI) {
#pragma unroll
        for (int v = 0; v < VEC; v++) {
            acc[v] += bias[lane * VEC + v];
            acc[v] = fmaxf(acc[v], 0.f);
        }
    }
    if (VEC == 4) *(float4*)q = make_float4(acc[0], acc[1], acc[2], acc[3]);
    else          *(float2*)q = make_float2(acc[0], acc[1]);
}

// ----------------------- mma.sync split-bf16 GEMM ---------------------------
// C[N, BN] = A[N, K] @ W[K, BN] (+bias, relu). Block: 128 rows x 64 cols
// (blockIdx.y selects 64-col half for BN=128). 256 threads = 8 warps; warp w
// computes rows [w*16, w*16+16) x 64 cols = 8 m16n8k16 accumulators.
// K-expansion x3: A' cols [3k,3k+1,3k+2] = [hiA, hiA, loA];
//                 B' rows same           = [hiB, loB, hiB].
template <int K, int BN, bool EPI, int IN, int OUT>
__global__ __launch_bounds__(256, 1)
void k_gemm_mma(const float* __restrict__ Aext, const float* __restrict__ W,
                const float* __restrict__ bias) {
    constexpr int BM = 128, BNT = 64;
    constexpr int KC = 32;               // original k per chunk
    constexpr int KCE = KC * 3;          // 96 expanded
    constexpr int NCH = K / KC;
    constexpr int LDA = KCE + 8;         // padded stride (104)

    const float* __restrict__ A = (IN < 0) ? Aext : scratch<(IN < 0) ? 0 : IN>();
    float*       __restrict__ C = scratch<OUT>();

    __shared__ __nv_bfloat16 As[BM][LDA];    // ~26.6 KB
    __shared__ __nv_bfloat16 Bs[BNT][LDA];   // ~13.3 KB

    int tid = threadIdx.x;
    int wid = tid >> 5;
    int lane = tid & 31;
    int g = lane >> 2;                   // group id 0..7
    int tq = lane & 3;                   // thread in quad
    int row0 = blockIdx.x * BM;
    int n0 = blockIdx.y * BNT;

    float acc[8][4];
#pragma unroll
    for (int i = 0; i < 8; i++)
#pragma unroll
        for (int j = 0; j < 4; j++) acc[i][j] = 0.f;

    for (int ch = 0; ch < NCH; ch++) {
        // --- A chunk: BM x KC fp32, expand x3 into As ---
        for (int i = tid; i < BM * KC; i += 256) {
            int m = i >> 5;              // 0..127
            int k = i & 31;
            float a = 0.f;
            int r = row0 + m;
            if (r < NN) a = A[(size_t)r * K + ch * KC + k];
            __nv_bfloat16 vh = __float2bfloat16(a);
            __nv_bfloat16 vl = __float2bfloat16(a - __bfloat162float(vh));
            As[m][3 * k + 0] = vh;
            As[m][3 * k + 1] = vh;
            As[m][3 * k + 2] = vl;
        }
        // --- B chunk: KC x BNT fp32 (W[ch*KC+k][n0+n]), n-major into Bs ---
        for (int i = tid; i < BNT * KC; i += 256) {
            int n = i & 63;
            int k = i >> 6;
            float b = W[(size_t)(ch * KC + k) * BN + n0 + n];
            __nv_bfloat16 vh = __float2bfloat16(b);
            __nv_bfloat16 vl = __float2bfloat16(b - __bfloat162float(vh));
            Bs[n][3 * k + 0] = vh;
            Bs[n][3 * k + 1] = vl;
            Bs[n][3 * k + 2] = vh;
        }
        __syncthreads();

        int m0 = wid * 16;
#pragma unroll
        for (int ks = 0; ks < KCE / 16; ks++) {      // 6 k-steps
            int k0 = ks * 16;
            uint32_t a[4];
            a[0] = *(const uint32_t*)&As[m0 + g][k0 + tq * 2];
            a[1] = *(const uint32_t*)&As[m0 + g + 8][k0 + tq * 2];
            a[2] = *(const uint32_t*)&As[m0 + g][k0 + tq * 2 + 8];
            a[3] = *(const uint32_t*)&As[m0 + g + 8][k0 + tq * 2 + 8];
#pragma unroll
            for (int nt = 0; nt < 8; nt++) {
                uint32_t b0 = *(const uint32_t*)&Bs[nt * 8 + g][k0 + tq * 2];
                uint32_t b1 = *(const uint32_t*)&Bs[nt * 8 + g][k0 + tq * 2 + 8];
                mma_16816(acc[nt], a, b0, b1);
            }
        }
        __syncthreads();
    }

    // --- epilogue ---
    int r_lo = row0 + wid * 16 + g;
    int r_hi = r_lo + 8;
#pragma unroll
    for (int nt = 0; nt < 8; nt++) {
        int col = nt * 8 + tq * 2;
        float2 v0 = make_float2(acc[nt][0], acc[nt][1]);
        float2 v1 = make_float2(acc[nt][2], acc[nt][3]);
        if (EPI) {
            float bA = bias[n0 + col], bB = bias[n0 + col + 1];
            v0.x = fmaxf(v0.x + bA, 0.f); v0.y = fmaxf(v0.y + bB, 0.f);
            v1.x = fmaxf(v1.x + bA, 0.f); v1.y = fmaxf(v1.y + bB, 0.f);
        }
        if (r_lo < NN) *(float2*)(C + (size_t)r_lo * BN + n0 + col) = v0;
        if (r_hi < NN) *(float2*)(C + (size_t)r_hi * BN + n0 + col) = v1;
    }
}

// ------------------------------- mean pooling -------------------------------
__global__ void k_pool(const int* __restrict__ batch) {
    const float* __restrict__ h = g_bufC;
    constexpr int CH = 64;
    int n0 = blockIdx.x * CH;
    int t  = threadIdx.x;                 // 128 = feature
    if (n0 >= NN) return;
    int is64 = g_b64;
    int end = n0 + CH; if (end > NN) end = NN;
    float acc = 0.f, cacc = 0.f;
    int cur = clampi(load_idx(batch, n0, is64), NG);
    for (int n = n0; n < end; n++) {
        int g = clampi(load_idx(batch, n, is64), NG);
        if (g != cur) {
            atomicAdd(&g_pool[cur * 128 + t], acc);
            if (t == 0) atomicAdd(&g_cnt[cur], cacc);
            acc = 0.f; cacc = 0.f; cur = g;
        }
        acc  += h[(size_t)n * 128 + t];
        cacc += 1.f;
    }
    atomicAdd(&g_pool[cur * 128 + t], acc);
    if (t == 0) atomicAdd(&g_cnt[cur], cacc);
}

// --------------------------- classifier + log_softmax -----------------------
__global__ void k_cls(const float* __restrict__ Wc1, const float* __restrict__ bc1,
                      const float* __restrict__ Wc2, const float* __restrict__ bc2,
                      float* __restrict__ out) {
    int g = blockIdx.x;
    int t = threadIdx.x;                  // 128
    __shared__ float p[128];
    __shared__ float z[64];
    __shared__ float lo[OUTF];
    float c = fmaxf(g_cnt[g], 1.f);
    p[t] = g_pool[g * 128 + t] / c;
    __syncthreads();
    if (t < 64) {
        float a = bc1[t];
#pragma unroll 8
        for (int k = 0; k < 128; k++) a += p[k] * Wc1[k * 64 + t];
        z[t] = fmaxf(a, 0.f);
    }
    __syncthreads();
    if (t < OUTF) {
        float a = bc2[t];
#pragma unroll 8
        for (int k = 0; k < 64; k++) a += z[k] * Wc2[k * OUTF + t];
        lo[t] = a;
    }
    __syncthreads();
    if (t < OUTF) {
        float m = lo[0];
#pragma unroll
        for (int i = 1; i < OUTF; i++) m = fmaxf(m, lo[i]);
        float s = 0.f;
#pragma unroll
        for (int i = 0; i < OUTF; i++) s += expf(lo[i] - m);
        out[g * OUTF + t] = lo[t] - m - logf(s);
    }
}

// --------------------------------- launch -----------------------------------
extern "C" void kernel_launch(void* const* d_in, const int* in_sizes, int n_in,
                              void* d_out, int out_size) {
    const float* x     = (const float*)d_in[0];
    const int*   ei    = (const int*)d_in[1];
    const int*   batch = (const int*)d_in[2];
    const float* W1  = (const float*)d_in[3];
    const float* b1  = (const float*)d_in[4];
    const float* W2  = (const float*)d_in[5];
    const float* b2  = (const float*)d_in[6];
    const float* W3  = (const float*)d_in[7];
    const float* b3  = (const float*)d_in[8];
    const float* Wc1 = (const float*)d_in[9];
    const float* bc1 = (const float*)d_in[10];
    const float* Wc2 = (const float*)d_in[11];
    const float* bc2 = (const float*)d_in[12];
    float* out = (float*)d_out;

    const int GBM = (NN + 127) / 128;       // gemm tile rows (782)
    const int SP  = (NN + 3) / 4;           // spmm blocks (4 warps/block)

    k_detect  <<<1, 128>>>(ei, batch);
    k_init    <<<(NN + 255) / 256, 256>>>();
    k_count   <<<(NE + 255) / 256, 256>>>(ei);
    // GEMM1 has no CSR dependency; launch slot 3 = ncu capture slot
    k_gemm_mma<128, 64, false, -1, 0><<<dim3(GBM, 1), 256>>>(x, W1, nullptr);
    k_part    <<<SCAN_NB, SCAN_B>>>();
    k_scanpart<<<1, 256>>>();
    k_write   <<<SCAN_NB, SCAN_B>>>();
    k_fill    <<<(NTOT + 255) / 256, 256>>>(ei);

    // buffers: 0=A(64w) 1=B(64w) 2=C(128w) 3=D(128w)
    // L1: h1 = relu(CSR·A + b1) -> B
    k_spmm<64, true, 0, 1><<<SP, 128>>>(b1);
    // L2: s2 = CSR·B -> A ; h2 = relu(A @ W2 + b2) -> C
    k_spmm<64, false, 1, 0><<<SP, 128>>>(nullptr);
    k_gemm_mma<64, 128, true, 0, 2><<<dim3(GBM, 2), 256>>>(nullptr, W2, b2);
    // L3: t3 = C @ W3 -> D ; h3 = relu(CSR·D + b3) -> C
    k_gemm_mma<128, 128, false, 2, 3><<<dim3(GBM, 2), 256>>>(nullptr, W3, nullptr);
    k_spmm<128, true, 3, 2><<<SP, 128>>>(b3);

    k_pool<<<(NN + 63) / 64, 128>>>(batch);
    k_cls <<<NG, 128>>>(Wc1, bc1, Wc2, bc2, out);
}

// round 13
// speedup vs baseline: 1.0631x; 1.0631x over previous
#include <cuda_runtime.h>
#include <cuda_bf16.h>
#include <math.h>
#include <stdint.h>

// ---------------------------------------------------------------------------
// GCN_Protein: 3x GCNConv -> mean pool -> MLP -> log_softmax
//   R12: HMMA GEMM throughput fixes:
//        - ldmatrix.x4 fragment loads (was 20 scalar LDS.32 / warp-k-step)
//        - segmented K-expansion [hiA|hiA|loA] x [hiB|loB|hiB], packed u32
//          bf16x2 conversion stores
//        - __launch_bounds__(256,2): 2 CTAs/SM for latency hiding
//   SpMM / CSR build / pool / cls unchanged.
// ---------------------------------------------------------------------------

#define NN 100000
#define NE 1600000
#define NTOT (NN + NE)
#define NG 512
#define OUTF 10

#define SCAN_B 512
#define SCAN_NB ((NN + SCAN_B - 1) / SCAN_B)   // 196

// ------------------------- scratch (device globals) ------------------------
__device__ int   g_e64;
__device__ int   g_b64;
__device__ int   g_deg[NN];
__device__ int   g_rowptr[NN + 1];
__device__ int   g_cursor[NN];
__device__ float g_dinv[NN];
__device__ int   g_part[SCAN_NB];
__device__ int   g_partoff[SCAN_NB];
__device__ int2  g_colw[NTOT];               // packed {col, float_as_int(wgt)}
__device__ float g_bufA[(size_t)NN * 64];
__device__ float g_bufB[(size_t)NN * 64];
__device__ float g_bufC[(size_t)NN * 128];
__device__ float g_bufD[(size_t)NN * 128];
__device__ float g_pool[NG * 128];
__device__ float g_cnt[NG];

template <int ID>
__device__ __forceinline__ float* scratch() {
    if (ID == 0) return g_bufA;
    if (ID == 1) return g_bufB;
    if (ID == 2) return g_bufC;
    return g_bufD;
}

__device__ __forceinline__ int clampi(int v, int hi) {
    return v < 0 ? 0 : (v >= hi ? hi - 1 : v);
}

__device__ __forceinline__ int load_idx(const int* __restrict__ p, int i, int is64) {
    return is64 ? p[2 * i] : p[i];
}

// ------------------------------ mma helpers ---------------------------------
__device__ __forceinline__ void mma_16816(float* c, const uint32_t* a,
                                          uint32_t b0, uint32_t b1) {
    asm volatile(
        "mma.sync.aligned.m16n8k16.row.col.f32.bf16.bf16.f32 "
        "{%0,%1,%2,%3}, {%4,%5,%6,%7}, {%8,%9}, {%0,%1,%2,%3};"
        : "+f"(c[0]), "+f"(c[1]), "+f"(c[2]), "+f"(c[3])
        : "r"(a[0]), "r"(a[1]), "r"(a[2]), "r"(a[3]), "r"(b0), "r"(b1));
}

__device__ __forceinline__ void ldmx4(uint32_t* r, uint32_t addr) {
    asm volatile(
        "ldmatrix.sync.aligned.m8n8.x4.shared.b16 {%0,%1,%2,%3}, [%4];"
        : "=r"(r[0]), "=r"(r[1]), "=r"(r[2]), "=r"(r[3]) : "r"(addr));
}

__device__ __forceinline__ uint32_t smem_u32(const void* p) {
    return (uint32_t)__cvta_generic_to_shared(p);
}

__device__ __forceinline__ uint32_t pk(__nv_bfloat16 a, __nv_bfloat16 b) {
    return (uint32_t)__bfloat16_as_ushort(a) | ((uint32_t)__bfloat16_as_ushort(b) << 16);
}

// ------------------------------ dtype detection ------------------------------
__global__ void k_detect(const int* __restrict__ ei, const int* __restrict__ batch) {
    __shared__ int nz_e, nz_b;
    int t = threadIdx.x;                       // 128 threads
    if (t == 0) { nz_e = 0; nz_b = 0; }
    __syncthreads();
    long long stride = (2LL * NE) / 128;
    int we = (int)((long long)t * stride) | 1;
    if (ei[we] != 0) atomicAdd(&nz_e, 1);
    int wb = (NN - 1 - 2 * t) | 1;
    if (batch[wb] != 0) atomicAdd(&nz_b, 1);
    __syncthreads();
    if (t == 0) { g_e64 = (nz_e == 0); g_b64 = (nz_b == 0); }
}

// ------------------------------ preprocessing ------------------------------
__global__ void k_init() {
    int i = blockIdx.x * blockDim.x + threadIdx.x;
    if (i < NN) { g_deg[i] = 1; g_cursor[i] = 0; }   // self-loop contributes 1
    if (i < NG * 128) g_pool[i] = 0.f;
    if (i < NG) g_cnt[i] = 0.f;
}

__global__ void k_count(const int* __restrict__ ei) {
    int e = blockIdx.x * blockDim.x + threadIdx.x;
    if (e < NE) {
        int d = clampi(load_idx(ei, NE + e, g_e64), NN);
        atomicAdd(&g_deg[d], 1);
    }
}

__global__ void k_part() {
    __shared__ int red[SCAN_B];
    int t = threadIdx.x;
    int i = blockIdx.x * SCAN_B + t;
    red[t] = (i < NN) ? g_deg[i] : 0;
    __syncthreads();
#pragma unroll
    for (int off = SCAN_B / 2; off > 0; off >>= 1) {
        if (t < off) red[t] += red[t + off];
        __syncthreads();
    }
    if (t == 0) g_part[blockIdx.x] = red[0];
}

__global__ void k_scanpart() {
    __shared__ int s[256];
    int t = threadIdx.x;
    int v = (t < SCAN_NB) ? g_part[t] : 0;
    s[t] = v;
    __syncthreads();
#pragma unroll
    for (int off = 1; off < 256; off <<= 1) {
        int x = (t >= off) ? s[t - off] : 0;
        __syncthreads();
        s[t] += x;
        __syncthreads();
    }
    if (t < SCAN_NB) g_partoff[t] = s[t] - v;  // exclusive
}

__global__ void k_write() {
    __shared__ int s[SCAN_B];
    int t = threadIdx.x;
    int i = blockIdx.x * SCAN_B + t;
    int v = (i < NN) ? g_deg[i] : 0;
    s[t] = v;
    __syncthreads();
#pragma unroll
    for (int off = 1; off < SCAN_B; off <<= 1) {
        int x = (t >= off) ? s[t - off] : 0;
        __syncthreads();
        s[t] += x;
        __syncthreads();
    }
    int base = g_partoff[blockIdx.x];
    if (i < NN) {
        g_rowptr[i] = base + s[t] - v;         // exclusive
        g_dinv[i]   = rsqrtf((float)v);
    }
    if (i == NN - 1) g_rowptr[NN] = base + s[t];
}

__global__ void k_fill(const int* __restrict__ ei) {
    int idx = blockIdx.x * blockDim.x + threadIdx.x;
    if (idx < NN) {
        int pos = g_rowptr[idx] + atomicAdd(&g_cursor[idx], 1);
        float di = g_dinv[idx];
        g_colw[pos] = make_int2(idx, __float_as_int(di * di));
    } else if (idx < NTOT) {
        int e = idx - NN;
        int is64 = g_e64;
        int s = clampi(load_idx(ei, e, is64), NN);
        int d = clampi(load_idx(ei, NE + e, is64), NN);
        int pos = g_rowptr[d] + atomicAdd(&g_cursor[d], 1);
        g_colw[pos] = make_int2(s, __float_as_int(g_dinv[s] * g_dinv[d]));
    }
}

// ---------------------------------- SpMM -----------------------------------
template <int F, bool EPI, int IN, int OUT>
__global__ void k_spmm(const float* __restrict__ bias) {
    const float* __restrict__ hin  = scratch<IN>();
    float*       __restrict__ hout = scratch<OUT>();
    constexpr int VEC = F / 32;
    int warp = (blockIdx.x * blockDim.x + threadIdx.x) >> 5;
    int lane = threadIdx.x & 31;
    if (warp >= NN) return;
    int beg = g_rowptr[warp], end = g_rowptr[warp + 1];
    float acc[VEC];
#pragma unroll
    for (int v = 0; v < VEC; v++) acc[v] = 0.f;

    int k = beg;
    for (; k + 2 <= end; k += 2) {
        int2 e0 = g_colw[k];
        int2 e1 = g_colw[k + 1];
        float w0 = __int_as_float(e0.y);
        float w1 = __int_as_float(e1.y);
        const float* p0 = hin + (size_t)e0.x * F + lane * VEC;
        const float* p1 = hin + (size_t)e1.x * F + lane * VEC;
        if (VEC == 4) {
            float4 v0 = *(const float4*)p0;
            float4 v1 = *(const float4*)p1;
            acc[0] += w0 * v0.x; acc[1] += w0 * v0.y;
            acc[2] += w0 * v0.z; acc[3] += w0 * v0.w;
            acc[0] += w1 * v1.x; acc[1] += w1 * v1.y;
            acc[2] += w1 * v1.z; acc[3] += w1 * v1.w;
        } else {
            float2 v0 = *(const float2*)p0;
            float2 v1 = *(const float2*)p1;
            acc[0] += w0 * v0.x; acc[1] += w0 * v0.y;
            acc[0] += w1 * v1.x; acc[1] += w1 * v1.y;
        }
    }
    if (k < end) {
        int2 e0 = g_colw[k];
        float w0 = __int_as_float(e0.y);
        const float* p0 = hin + (size_t)e0.x * F + lane * VEC;
        if (VEC == 4) {
            float4 v0 = *(const float4*)p0;
            acc[0] += w0 * v0.x; acc[1] += w0 * v0.y;
            acc[2] += w0 * v0.z; acc[3] += w0 * v0.w;
        } else {
            float2 v0 = *(const float2*)p0;
            acc[0] += w0 * v0.x; acc[1] += w0 * v0.y;
        }
    }

    float* q = hout + (size_t)warp * F + lane * VEC;
    if (EPI) {
#pragma unroll
        for (int v = 0; v < VEC; v++) {
            acc[v] += bias[lane * VEC + v];
            acc[v] = fmaxf(acc[v], 0.f);
        }
    }
    if (VEC == 4) *(float4*)q = make_float4(acc[0], acc[1], acc[2], acc[3]);
    else          *(float2*)q = make_float2(acc[0], acc[1]);
}

// ----------------------- mma.sync split-bf16 GEMM ---------------------------
// C[N, BN] = A[N, K] @ W[K, BN] (+bias, relu). Block: 128 rows x 64 cols
// (blockIdx.y selects 64-col half for BN=128). 256 threads = 8 warps; warp w
// computes rows [w*16, w*16+16) x 64 cols = 8 m16n8k16 accumulators.
// Segmented K-expansion per 32-col chunk: expanded cols [0,32)=hiA/hiB,
// [32,64)=hiA/loB, [64,96)=loA/hiB  (C error ~2^-17, loA*loB dropped).
// Fragments loaded with ldmatrix.x4.
template <int K, int BN, bool EPI, int IN, int OUT>
__global__ __launch_bounds__(256, 2)
void k_gemm_mma(const float* __restrict__ Aext, const float* __restrict__ W,
                const float* __restrict__ bias) {
    constexpr int BM = 128, BNT = 64;
    constexpr int KC = 32;               // original k per chunk
    constexpr int KCE = KC * 3;          // 96 expanded
    constexpr int NCH = K / KC;
    constexpr int LDA = KCE + 8;         // padded stride (104 halves, 208 B)

    const float* __restrict__ A = (IN < 0) ? Aext : scratch<(IN < 0) ? 0 : IN>();
    float*       __restrict__ C = scratch<OUT>();

    __shared__ __align__(16) __nv_bfloat16 As[BM][LDA];    // 26624 B
    __shared__ __align__(16) __nv_bfloat16 Bs[BNT][LDA];   // 13312 B

    int tid = threadIdx.x;
    int wid = tid >> 5;
    int lane = tid & 31;
    int g = lane >> 2;                   // group id 0..7
    int tq = lane & 3;                   // thread in quad
    int row0 = blockIdx.x * BM;
    int n0 = blockIdx.y * BNT;

    // ldmatrix per-lane addressing: matrix = lane>>3, row-in-matrix = lane&7
    int mat = lane >> 3;
    int mrow = lane & 7;
    int a_roff = ((mat & 1) << 3) + mrow;   // A: mats {0,1}={m,m+8}@k0, {2,3}@k0+8
    int a_coff = (mat >> 1) << 3;
    int b_roff = ((mat >> 1) << 3) + mrow;  // B: mats {0,1}=nt0@{k0,k0+8}, {2,3}=nt1
    int b_coff = (mat & 1) << 3;

    float acc[8][4];
#pragma unroll
    for (int i = 0; i < 8; i++)
#pragma unroll
        for (int j = 0; j < 4; j++) acc[i][j] = 0.f;

    for (int ch = 0; ch < NCH; ch++) {
        // --- A chunk: BM x KC fp32 -> segmented hi/hi/lo, packed u32 stores ---
        for (int i = tid; i < BM * (KC / 2); i += 256) {
            int m = i >> 4;
            int k = (i & 15) * 2;
            float2 av = make_float2(0.f, 0.f);
            int r = row0 + m;
            if (r < NN) av = *(const float2*)(A + (size_t)r * K + ch * KC + k);
            __nv_bfloat16 h0 = __float2bfloat16(av.x);
            __nv_bfloat16 l0 = __float2bfloat16(av.x - __bfloat162float(h0));
            __nv_bfloat16 h1 = __float2bfloat16(av.y);
            __nv_bfloat16 l1 = __float2bfloat16(av.y - __bfloat162float(h1));
            uint32_t hh = pk(h0, h1), ll = pk(l0, l1);
            *(uint32_t*)&As[m][k] = hh;
            *(uint32_t*)&As[m][KC + k] = hh;
            *(uint32_t*)&As[m][2 * KC + k] = ll;
        }
        // --- B chunk: KC x BNT fp32 -> segmented hi/lo/hi ---
        for (int i = tid; i < BNT * (KC / 2); i += 256) {
            int n = i & 63;
            int k = (i >> 6) * 2;
            float b0v = W[(size_t)(ch * KC + k) * BN + n0 + n];
            float b1v = W[(size_t)(ch * KC + k + 1) * BN + n0 + n];
            __nv_bfloat16 h0 = __float2bfloat16(b0v);
            __nv_bfloat16 l0 = __float2bfloat16(b0v - __bfloat162float(h0));
            __nv_bfloat16 h1 = __float2bfloat16(b1v);
            __nv_bfloat16 l1 = __float2bfloat16(b1v - __bfloat162float(h1));
            uint32_t hh = pk(h0, h1), ll = pk(l0, l1);
            *(uint32_t*)&Bs[n][k] = hh;
            *(uint32_t*)&Bs[n][KC + k] = ll;
            *(uint32_t*)&Bs[n][2 * KC + k] = hh;
        }
        __syncthreads();

        int m0 = wid * 16;
#pragma unroll
        for (int ks = 0; ks < KCE / 16; ks++) {      // 6 k-steps
            int k0 = ks * 16;
            uint32_t a[4];
            ldmx4(a, smem_u32(&As[m0 + a_roff][k0 + a_coff]));
#pragma unroll
            for (int ntp = 0; ntp < 4; ntp++) {
                uint32_t b[4];
                ldmx4(b, smem_u32(&Bs[ntp * 16 + b_roff][k0 + b_coff]));
                mma_16816(acc[2 * ntp + 0], a, b[0], b[1]);
                mma_16816(acc[2 * ntp + 1], a, b[2], b[3]);
            }
        }
        __syncthreads();
    }

    // --- epilogue ---
    int r_lo = row0 + wid * 16 + g;
    int r_hi = r_lo + 8;
#pragma unroll
    for (int nt = 0; nt < 8; nt++) {
        int col = nt * 8 + tq * 2;
        float2 v0 = make_float2(acc[nt][0], acc[nt][1]);
        float2 v1 = make_float2(acc[nt][2], acc[nt][3]);
        if (EPI) {
            float bA = bias[n0 + col], bB = bias[n0 + col + 1];
            v0.x = fmaxf(v0.x + bA, 0.f); v0.y = fmaxf(v0.y + bB, 0.f);
            v1.x = fmaxf(v1.x + bA, 0.f); v1.y = fmaxf(v1.y + bB, 0.f);
        }
        if (r_lo < NN) *(float2*)(C + (size_t)r_lo * BN + n0 + col) = v0;
        if (r_hi < NN) *(float2*)(C + (size_t)r_hi * BN + n0 + col) = v1;
    }
}

// ------------------------------- mean pooling -------------------------------
__global__ void k_pool(const int* __restrict__ batch) {
    const float* __restrict__ h = g_bufC;
    constexpr int CH = 64;
    int n0 = blockIdx.x * CH;
    int t  = threadIdx.x;                 // 128 = feature
    if (n0 >= NN) return;
    int is64 = g_b64;
    int end = n0 + CH; if (end > NN) end = NN;
    float acc = 0.f, cacc = 0.f;
    int cur = clampi(load_idx(batch, n0, is64), NG);
    for (int n = n0; n < end; n++) {
        int g = clampi(load_idx(batch, n, is64), NG);
        if (g != cur) {
            atomicAdd(&g_pool[cur * 128 + t], acc);
            if (t == 0) atomicAdd(&g_cnt[cur], cacc);
            acc = 0.f; cacc = 0.f; cur = g;
        }
        acc  += h[(size_t)n * 128 + t];
        cacc += 1.f;
    }
    atomicAdd(&g_pool[cur * 128 + t], acc);
    if (t == 0) atomicAdd(&g_cnt[cur], cacc);
}

// --------------------------- classifier + log_softmax -----------------------
__global__ void k_cls(const float* __restrict__ Wc1, const float* __restrict__ bc1,
                      const float* __restrict__ Wc2, const float* __restrict__ bc2,
                      float* __restrict__ out) {
    int g = blockIdx.x;
    int t = threadIdx.x;                  // 128
    __shared__ float p[128];
    __shared__ float z[64];
    __shared__ float lo[OUTF];
    float c = fmaxf(g_cnt[g], 1.f);
    p[t] = g_pool[g * 128 + t] / c;
    __syncthreads();
    if (t < 64) {
        float a = bc1[t];
#pragma unroll 8
        for (int k = 0; k < 128; k++) a += p[k] * Wc1[k * 64 + t];
        z[t] = fmaxf(a, 0.f);
    }
    __syncthreads();
    if (t < OUTF) {
        float a = bc2[t];
#pragma unroll 8
        for (int k = 0; k < 64; k++) a += z[k] * Wc2[k * OUTF + t];
        lo[t] = a;
    }
    __syncthreads();
    if (t < OUTF) {
        float m = lo[0];
#pragma unroll
        for (int i = 1; i < OUTF; i++) m = fmaxf(m, lo[i]);
        float s = 0.f;
#pragma unroll
        for (int i = 0; i < OUTF; i++) s += expf(lo[i] - m);
        out[g * OUTF + t] = lo[t] - m - logf(s);
    }
}

// --------------------------------- launch -----------------------------------
extern "C" void kernel_launch(void* const* d_in, const int* in_sizes, int n_in,
                              void* d_out, int out_size) {
    const float* x     = (const float*)d_in[0];
    const int*   ei    = (const int*)d_in[1];
    const int*   batch = (const int*)d_in[2];
    const float* W1  = (const float*)d_in[3];
    const float* b1  = (const float*)d_in[4];
    const float* W2  = (const float*)d_in[5];
    const float* b2  = (const float*)d_in[6];
    const float* W3  = (const float*)d_in[7];
    const float* b3  = (const float*)d_in[8];
    const float* Wc1 = (const float*)d_in[9];
    const float* bc1 = (const float*)d_in[10];
    const float* Wc2 = (const float*)d_in[11];
    const float* bc2 = (const float*)d_in[12];
    float* out = (float*)d_out;

    const int GBM = (NN + 127) / 128;       // gemm tile rows (782)
    const int SP  = (NN + 3) / 4;           // spmm blocks (4 warps/block)

    k_detect  <<<1, 128>>>(ei, batch);
    k_init    <<<(NN + 255) / 256, 256>>>();
    k_count   <<<(NE + 255) / 256, 256>>>(ei);
    // GEMM1 has no CSR dependency; launch slot 3 = ncu capture slot
    k_gemm_mma<128, 64, false, -1, 0><<<dim3(GBM, 1), 256>>>(x, W1, nullptr);
    k_part    <<<SCAN_NB, SCAN_B>>>();
    k_scanpart<<<1, 256>>>();
    k_write   <<<SCAN_NB, SCAN_B>>>();
    k_fill    <<<(NTOT + 255) / 256, 256>>>(ei);

    // buffers: 0=A(64w) 1=B(64w) 2=C(128w) 3=D(128w)
    // L1: h1 = relu(CSR·A + b1) -> B
    k_spmm<64, true, 0, 1><<<SP, 128>>>(b1);
    // L2: s2 = CSR·B -> A ; h2 = relu(A @ W2 + b2) -> C
    k_spmm<64, false, 1, 0><<<SP, 128>>>(nullptr);
    k_gemm_mma<64, 128, true, 0, 2><<<dim3(GBM, 2), 256>>>(nullptr, W2, b2);
    // L3: t3 = C @ W3 -> D ; h3 = relu(CSR·D + b3) -> C
    k_gemm_mma<128, 128, false, 2, 3><<<dim3(GBM, 2), 256>>>(nullptr, W3, nullptr);
    k_spmm<128, true, 3, 2><<<SP, 128>>>(b3);

    k_pool<<<(NN + 63) / 64, 128>>>(batch);
    k_cls <<<NG, 128>>>(Wc1, bc1, Wc2, bc2, out);
}

// round 14
// speedup vs baseline: 1.2562x; 1.1816x over previous
#include <cuda_runtime.h>
#include <cuda_bf16.h>
#include <math.h>
#include <stdint.h>

// ---------------------------------------------------------------------------
// GCN_Protein: 3x GCNConv -> mean pool -> MLP -> log_softmax
//   R13: GEMM pipeline restructure:
//        - no hi-duplication: smem holds [hi|lo] segments; 3 fragment passes
//          per chunk (Ahi*Bhi + Ahi*Blo + Alo*Bhi) via segment offsets
//        - double-buffered smem (KC=16, 2x15.4KB) + software pipeline:
//          LDG chunk ch+1 overlaps MMA of chunk ch; 1 sync/chunk
//   SpMM / CSR build / pool / cls unchanged.
// ---------------------------------------------------------------------------

#define NN 100000
#define NE 1600000
#define NTOT (NN + NE)
#define NG 512
#define OUTF 10

#define SCAN_B 512
#define SCAN_NB ((NN + SCAN_B - 1) / SCAN_B)   // 196

// ------------------------- scratch (device globals) ------------------------
__device__ int   g_e64;
__device__ int   g_b64;
__device__ int   g_deg[NN];
__device__ int   g_rowptr[NN + 1];
__device__ int   g_cursor[NN];
__device__ float g_dinv[NN];
__device__ int   g_part[SCAN_NB];
__device__ int   g_partoff[SCAN_NB];
__device__ int2  g_colw[NTOT];               // packed {col, float_as_int(wgt)}
__device__ float g_bufA[(size_t)NN * 64];
__device__ float g_bufB[(size_t)NN * 64];
__device__ float g_bufC[(size_t)NN * 128];
__device__ float g_bufD[(size_t)NN * 128];
__device__ float g_pool[NG * 128];
__device__ float g_cnt[NG];

template <int ID>
__device__ __forceinline__ float* scratch() {
    if (ID == 0) return g_bufA;
    if (ID == 1) return g_bufB;
    if (ID == 2) return g_bufC;
    return g_bufD;
}

__device__ __forceinline__ int clampi(int v, int hi) {
    return v < 0 ? 0 : (v >= hi ? hi - 1 : v);
}

__device__ __forceinline__ int load_idx(const int* __restrict__ p, int i, int is64) {
    return is64 ? p[2 * i] : p[i];
}

// ------------------------------ mma helpers ---------------------------------
__device__ __forceinline__ void mma_16816(float* c, const uint32_t* a,
                                          uint32_t b0, uint32_t b1) {
    asm volatile(
        "mma.sync.aligned.m16n8k16.row.col.f32.bf16.bf16.f32 "
        "{%0,%1,%2,%3}, {%4,%5,%6,%7}, {%8,%9}, {%0,%1,%2,%3};"
        : "+f"(c[0]), "+f"(c[1]), "+f"(c[2]), "+f"(c[3])
        : "r"(a[0]), "r"(a[1]), "r"(a[2]), "r"(a[3]), "r"(b0), "r"(b1));
}

__device__ __forceinline__ void ldmx4(uint32_t* r, uint32_t addr) {
    asm volatile(
        "ldmatrix.sync.aligned.m8n8.x4.shared.b16 {%0,%1,%2,%3}, [%4];"
        : "=r"(r[0]), "=r"(r[1]), "=r"(r[2]), "=r"(r[3]) : "r"(addr));
}

__device__ __forceinline__ uint32_t smem_u32(const void* p) {
    return (uint32_t)__cvta_generic_to_shared(p);
}

__device__ __forceinline__ uint32_t pk(__nv_bfloat16 a, __nv_bfloat16 b) {
    return (uint32_t)__bfloat16_as_ushort(a) | ((uint32_t)__bfloat16_as_ushort(b) << 16);
}

__device__ __forceinline__ void split2(float x, float y, uint32_t& hh, uint32_t& ll) {
    __nv_bfloat16 h0 = __float2bfloat16(x);
    __nv_bfloat16 l0 = __float2bfloat16(x - __bfloat162float(h0));
    __nv_bfloat16 h1 = __float2bfloat16(y);
    __nv_bfloat16 l1 = __float2bfloat16(y - __bfloat162float(h1));
    hh = pk(h0, h1);
    ll = pk(l0, l1);
}

// ------------------------------ dtype detection ------------------------------
__global__ void k_detect(const int* __restrict__ ei, const int* __restrict__ batch) {
    __shared__ int nz_e, nz_b;
    int t = threadIdx.x;                       // 128 threads
    if (t == 0) { nz_e = 0; nz_b = 0; }
    __syncthreads();
    long long stride = (2LL * NE) / 128;
    int we = (int)((long long)t * stride) | 1;
    if (ei[we] != 0) atomicAdd(&nz_e, 1);
    int wb = (NN - 1 - 2 * t) | 1;
    if (batch[wb] != 0) atomicAdd(&nz_b, 1);
    __syncthreads();
    if (t == 0) { g_e64 = (nz_e == 0); g_b64 = (nz_b == 0); }
}

// ------------------------------ preprocessing ------------------------------
__global__ void k_init() {
    int i = blockIdx.x * blockDim.x + threadIdx.x;
    if (i < NN) { g_deg[i] = 1; g_cursor[i] = 0; }   // self-loop contributes 1
    if (i < NG * 128) g_pool[i] = 0.f;
    if (i < NG) g_cnt[i] = 0.f;
}

__global__ void k_count(const int* __restrict__ ei) {
    int e = blockIdx.x * blockDim.x + threadIdx.x;
    if (e < NE) {
        int d = clampi(load_idx(ei, NE + e, g_e64), NN);
        atomicAdd(&g_deg[d], 1);
    }
}

__global__ void k_part() {
    __shared__ int red[SCAN_B];
    int t = threadIdx.x;
    int i = blockIdx.x * SCAN_B + t;
    red[t] = (i < NN) ? g_deg[i] : 0;
    __syncthreads();
#pragma unroll
    for (int off = SCAN_B / 2; off > 0; off >>= 1) {
        if (t < off) red[t] += red[t + off];
        __syncthreads();
    }
    if (t == 0) g_part[blockIdx.x] = red[0];
}

__global__ void k_scanpart() {
    __shared__ int s[256];
    int t = threadIdx.x;
    int v = (t < SCAN_NB) ? g_part[t] : 0;
    s[t] = v;
    __syncthreads();
#pragma unroll
    for (int off = 1; off < 256; off <<= 1) {
        int x = (t >= off) ? s[t - off] : 0;
        __syncthreads();
        s[t] += x;
        __syncthreads();
    }
    if (t < SCAN_NB) g_partoff[t] = s[t] - v;  // exclusive
}

__global__ void k_write() {
    __shared__ int s[SCAN_B];
    int t = threadIdx.x;
    int i = blockIdx.x * SCAN_B + t;
    int v = (i < NN) ? g_deg[i] : 0;
    s[t] = v;
    __syncthreads();
#pragma unroll
    for (int off = 1; off < SCAN_B; off <<= 1) {
        int x = (t >= off) ? s[t - off] : 0;
        __syncthreads();
        s[t] += x;
        __syncthreads();
    }
    int base = g_partoff[blockIdx.x];
    if (i < NN) {
        g_rowptr[i] = base + s[t] - v;         // exclusive
        g_dinv[i]   = rsqrtf((float)v);
    }
    if (i == NN - 1) g_rowptr[NN] = base + s[t];
}

__global__ void k_fill(const int* __restrict__ ei) {
    int idx = blockIdx.x * blockDim.x + threadIdx.x;
    if (idx < NN) {
        int pos = g_rowptr[idx] + atomicAdd(&g_cursor[idx], 1);
        float di = g_dinv[idx];
        g_colw[pos] = make_int2(idx, __float_as_int(di * di));
    } else if (idx < NTOT) {
        int e = idx - NN;
        int is64 = g_e64;
        int s = clampi(load_idx(ei, e, is64), NN);
        int d = clampi(load_idx(ei, NE + e, is64), NN);
        int pos = g_rowptr[d] + atomicAdd(&g_cursor[d], 1);
        g_colw[pos] = make_int2(s, __float_as_int(g_dinv[s] * g_dinv[d]));
    }
}

// ---------------------------------- SpMM -----------------------------------
template <int F, bool EPI, int IN, int OUT>
__global__ void k_spmm(const float* __restrict__ bias) {
    const float* __restrict__ hin  = scratch<IN>();
    float*       __restrict__ hout = scratch<OUT>();
    constexpr int VEC = F / 32;
    int warp = (blockIdx.x * blockDim.x + threadIdx.x) >> 5;
    int lane = threadIdx.x & 31;
    if (warp >= NN) return;
    int beg = g_rowptr[warp], end = g_rowptr[warp + 1];
    float acc[VEC];
#pragma unroll
    for (int v = 0; v < VEC; v++) acc[v] = 0.f;

    int k = beg;
    for (; k + 2 <= end; k += 2) {
        int2 e0 = g_colw[k];
        int2 e1 = g_colw[k + 1];
        float w0 = __int_as_float(e0.y);
        float w1 = __int_as_float(e1.y);
        const float* p0 = hin + (size_t)e0.x * F + lane * VEC;
        const float* p1 = hin + (size_t)e1.x * F + lane * VEC;
        if (VEC == 4) {
            float4 v0 = *(const float4*)p0;
            float4 v1 = *(const float4*)p1;
            acc[0] += w0 * v0.x; acc[1] += w0 * v0.y;
            acc[2] += w0 * v0.z; acc[3] += w0 * v0.w;
            acc[0] += w1 * v1.x; acc[1] += w1 * v1.y;
            acc[2] += w1 * v1.z; acc[3] += w1 * v1.w;
        } else {
            float2 v0 = *(const float2*)p0;
            float2 v1 = *(const float2*)p1;
            acc[0] += w0 * v0.x; acc[1] += w0 * v0.y;
            acc[0] += w1 * v1.x; acc[1] += w1 * v1.y;
        }
    }
    if (k < end) {
        int2 e0 = g_colw[k];
        float w0 = __int_as_float(e0.y);
        const float* p0 = hin + (size_t)e0.x * F + lane * VEC;
        if (VEC == 4) {
            float4 v0 = *(const float4*)p0;
            acc[0] += w0 * v0.x; acc[1] += w0 * v0.y;
            acc[2] += w0 * v0.z; acc[3] += w0 * v0.w;
        } else {
            float2 v0 = *(const float2*)p0;
            acc[0] += w0 * v0.x; acc[1] += w0 * v0.y;
        }
    }

    float* q = hout + (size_t)warp * F + lane * VEC;
    if (EPI) {
#pragma unroll
        for (int v = 0; v < VEC; v++) {
            acc[v] += bias[lane * VEC + v];
            acc[v] = fmaxf(acc[v], 0.f);
        }
    }
    if (VEC == 4) *(float4*)q = make_float4(acc[0], acc[1], acc[2], acc[3]);
    else          *(float2*)q = make_float2(acc[0], acc[1]);
}

// ----------------------- mma.sync split-bf16 GEMM ---------------------------
// C[N, BN] = A[N, K] @ W[K, BN] (+bias, relu). Block: 128 rows x 64 cols
// (blockIdx.y selects 64-col half for BN=128). 256 threads = 8 warps; warp w
// computes rows [w*16, w*16+16) x 64 cols = 8 m16n8k16 accumulators.
// Smem stores [hi(KC) | lo(KC)] segments (no duplication); per chunk we run
// 3 fragment passes: Ahi*Bhi + Ahi*Blo + Alo*Bhi  (loA*loB ~2^-17 dropped).
// Double-buffered + software-pipelined: LDG of chunk ch+1 overlaps MMA of ch.
template <int K, int BN, bool EPI, int IN, int OUT>
__global__ __launch_bounds__(256, 2)
void k_gemm_mma(const float* __restrict__ Aext, const float* __restrict__ W,
                const float* __restrict__ bias) {
    constexpr int BM = 128, BNT = 64;
    constexpr int KC = 16;               // original k per chunk
    constexpr int NCH = K / KC;
    constexpr int LD = 2 * KC + 8;       // 40 halves (80 B rows, conflict-free)

    const float* __restrict__ A = (IN < 0) ? Aext : scratch<(IN < 0) ? 0 : IN>();
    float*       __restrict__ C = scratch<OUT>();

    __shared__ __align__(16) __nv_bfloat16 As[2][BM][LD];   // 2 x 10240 B
    __shared__ __align__(16) __nv_bfloat16 Bs[2][BNT][LD];  // 2 x 5120 B

    int tid = threadIdx.x;
    int wid = tid >> 5;
    int lane = tid & 31;
    int g = lane >> 2;                   // group id 0..7
    int tq = lane & 3;                   // thread in quad
    int row0 = blockIdx.x * BM;
    int n0 = blockIdx.y * BNT;

    // ldmatrix per-lane addressing
    int mat = lane >> 3;
    int mrow = lane & 7;
    int a_roff = ((mat & 1) << 3) + mrow;
    int a_coff = (mat >> 1) << 3;
    int b_roff = ((mat >> 1) << 3) + mrow;
    int b_coff = (mat & 1) << 3;

    // staging indices (A: 4 float2 per thread; B: 2 (k,k+1) pairs per thread)
    int am[4], ak[4];
#pragma unroll
    for (int j = 0; j < 4; j++) {
        int i = tid + 256 * j;
        am[j] = i >> 3;                  // row 0..127
        ak[j] = (i & 7) * 2;             // col 0..14
    }
    int bn[2], bk[2];
#pragma unroll
    for (int j = 0; j < 2; j++) {
        int i = tid + 256 * j;
        bn[j] = i & 63;
        bk[j] = (i >> 6) * 2;
    }

    float2 aR[4];
    float  bR[2][2];

    auto ldg_chunk = [&](int ch) {
#pragma unroll
        for (int j = 0; j < 4; j++) {
            int r = row0 + am[j];
            aR[j] = (r < NN) ? *(const float2*)(A + (size_t)r * K + ch * KC + ak[j])
                             : make_float2(0.f, 0.f);
        }
#pragma unroll
        for (int j = 0; j < 2; j++) {
            bR[j][0] = W[(size_t)(ch * KC + bk[j]) * BN + n0 + bn[j]];
            bR[j][1] = W[(size_t)(ch * KC + bk[j] + 1) * BN + n0 + bn[j]];
        }
    };

    auto cvt_chunk = [&](int buf) {
#pragma unroll
        for (int j = 0; j < 4; j++) {
            uint32_t hh, ll;
            split2(aR[j].x, aR[j].y, hh, ll);
            *(uint32_t*)&As[buf][am[j]][ak[j]] = hh;
            *(uint32_t*)&As[buf][am[j]][KC + ak[j]] = ll;
        }
#pragma unroll
        for (int j = 0; j < 2; j++) {
            uint32_t hh, ll;
            split2(bR[j][0], bR[j][1], hh, ll);
            *(uint32_t*)&Bs[buf][bn[j]][bk[j]] = hh;
            *(uint32_t*)&Bs[buf][bn[j]][KC + bk[j]] = ll;
        }
    };

    float acc[8][4];
#pragma unroll
    for (int i = 0; i < 8; i++)
#pragma unroll
        for (int j = 0; j < 4; j++) acc[i][j] = 0.f;

    // prologue
    ldg_chunk(0);
    cvt_chunk(0);
    __syncthreads();

    int m0 = wid * 16;
    for (int ch = 0; ch < NCH; ch++) {
        int buf = ch & 1;
        if (ch + 1 < NCH) ldg_chunk(ch + 1);    // LDGs overlap mma below

        uint32_t aH[4], aL[4];
        ldmx4(aH, smem_u32(&As[buf][m0 + a_roff][a_coff]));
        ldmx4(aL, smem_u32(&As[buf][m0 + a_roff][KC + a_coff]));
#pragma unroll
        for (int ntp = 0; ntp < 4; ntp++) {
            uint32_t bH[4], bL[4];
            ldmx4(bH, smem_u32(&Bs[buf][ntp * 16 + b_roff][b_coff]));
            ldmx4(bL, smem_u32(&Bs[buf][ntp * 16 + b_roff][KC + b_coff]));
            mma_16816(acc[2 * ntp + 0], aH, bH[0], bH[1]);
            mma_16816(acc[2 * ntp + 1], aH, bH[2], bH[3]);
            mma_16816(acc[2 * ntp + 0], aH, bL[0], bL[1]);
            mma_16816(acc[2 * ntp + 1], aH, bL[2], bL[3]);
            mma_16816(acc[2 * ntp + 0], aL, bH[0], bH[1]);
            mma_16816(acc[2 * ntp + 1], aL, bH[2], bH[3]);
        }

        if (ch + 1 < NCH) cvt_chunk(1 - buf);   // writes other buffer
        __syncthreads();
    }

    // --- epilogue ---
    int r_lo = row0 + wid * 16 + g;
    int r_hi = r_lo + 8;
#pragma unroll
    for (int nt = 0; nt < 8; nt++) {
        int col = nt * 8 + tq * 2;
        float2 v0 = make_float2(acc[nt][0], acc[nt][1]);
        float2 v1 = make_float2(acc[nt][2], acc[nt][3]);
        if (EPI) {
            float bA = bias[n0 + col], bB = bias[n0 + col + 1];
            v0.x = fmaxf(v0.x + bA, 0.f); v0.y = fmaxf(v0.y + bB, 0.f);
            v1.x = fmaxf(v1.x + bA, 0.f); v1.y = fmaxf(v1.y + bB, 0.f);
        }
        if (r_lo < NN) *(float2*)(C + (size_t)r_lo * BN + n0 + col) = v0;
        if (r_hi < NN) *(float2*)(C + (size_t)r_hi * BN + n0 + col) = v1;
    }
}

// ------------------------------- mean pooling -------------------------------
__global__ void k_pool(const int* __restrict__ batch) {
    const float* __restrict__ h = g_bufC;
    constexpr int CH = 64;
    int n0 = blockIdx.x * CH;
    int t  = threadIdx.x;                 // 128 = feature
    if (n0 >= NN) return;
    int is64 = g_b64;
    int end = n0 + CH; if (end > NN) end = NN;
    float acc = 0.f, cacc = 0.f;
    int cur = clampi(load_idx(batch, n0, is64), NG);
    for (int n = n0; n < end; n++) {
        int g = clampi(load_idx(batch, n, is64), NG);
        if (g != cur) {
            atomicAdd(&g_pool[cur * 128 + t], acc);
            if (t == 0) atomicAdd(&g_cnt[cur], cacc);
            acc = 0.f; cacc = 0.f; cur = g;
        }
        acc  += h[(size_t)n * 128 + t];
        cacc += 1.f;
    }
    atomicAdd(&g_pool[cur * 128 + t], acc);
    if (t == 0) atomicAdd(&g_cnt[cur], cacc);
}

// --------------------------- classifier + log_softmax -----------------------
__global__ void k_cls(const float* __restrict__ Wc1, const float* __restrict__ bc1,
                      const float* __restrict__ Wc2, const float* __restrict__ bc2,
                      float* __restrict__ out) {
    int g = blockIdx.x;
    int t = threadIdx.x;                  // 128
    __shared__ float p[128];
    __shared__ float z[64];
    __shared__ float lo[OUTF];
    float c = fmaxf(g_cnt[g], 1.f);
    p[t] = g_pool[g * 128 + t] / c;
    __syncthreads();
    if (t < 64) {
        float a = bc1[t];
#pragma unroll 8
        for (int k = 0; k < 128; k++) a += p[k] * Wc1[k * 64 + t];
        z[t] = fmaxf(a, 0.f);
    }
    __syncthreads();
    if (t < OUTF) {
        float a = bc2[t];
#pragma unroll 8
        for (int k = 0; k < 64; k++) a += z[k] * Wc2[k * OUTF + t];
        lo[t] = a;
    }
    __syncthreads();
    if (t < OUTF) {
        float m = lo[0];
#pragma unroll
        for (int i = 1; i < OUTF; i++) m = fmaxf(m, lo[i]);
        float s = 0.f;
#pragma unroll
        for (int i = 0; i < OUTF; i++) s += expf(lo[i] - m);
        out[g * OUTF + t] = lo[t] - m - logf(s);
    }
}

// --------------------------------- launch -----------------------------------
extern "C" void kernel_launch(void* const* d_in, const int* in_sizes, int n_in,
                              void* d_out, int out_size) {
    const float* x     = (const float*)d_in[0];
    const int*   ei    = (const int*)d_in[1];
    const int*   batch = (const int*)d_in[2];
    const float* W1  = (const float*)d_in[3];
    const float* b1  = (const float*)d_in[4];
    const float* W2  = (const float*)d_in[5];
    const float* b2  = (const float*)d_in[6];
    const float* W3  = (const float*)d_in[7];
    const float* b3  = (const float*)d_in[8];
    const float* Wc1 = (const float*)d_in[9];
    const float* bc1 = (const float*)d_in[10];
    const float* Wc2 = (const float*)d_in[11];
    const float* bc2 = (const float*)d_in[12];
    float* out = (float*)d_out;

    const int GBM = (NN + 127) / 128;       // gemm tile rows (782)
    const int SP  = (NN + 3) / 4;           // spmm blocks (4 warps/block)

    k_detect  <<<1, 128>>>(ei, batch);
    k_init    <<<(NN + 255) / 256, 256>>>();
    k_count   <<<(NE + 255) / 256, 256>>>(ei);
    // GEMM1 has no CSR dependency; launch slot 3 = ncu capture slot
    k_gemm_mma<128, 64, false, -1, 0><<<dim3(GBM, 1), 256>>>(x, W1, nullptr);
    k_part    <<<SCAN_NB, SCAN_B>>>();
    k_scanpart<<<1, 256>>>();
    k_write   <<<SCAN_NB, SCAN_B>>>();
    k_fill    <<<(NTOT + 255) / 256, 256>>>(ei);

    // buffers: 0=A(64w) 1=B(64w) 2=C(128w) 3=D(128w)
    // L1: h1 = relu(CSR·A + b1) -> B
    k_spmm<64, true, 0, 1><<<SP, 128>>>(b1);
    // L2: s2 = CSR·B -> A ; h2 = relu(A @ W2 + b2) -> C
    k_spmm<64, false, 1, 0><<<SP, 128>>>(nullptr);
    k_gemm_mma<64, 128, true, 0, 2><<<dim3(GBM, 2), 256>>>(nullptr, W2, b2);
    // L3: t3 = C @ W3 -> D ; h3 = relu(CSR·D + b3) -> C
    k_gemm_mma<128, 128, false, 2, 3><<<dim3(GBM, 2), 256>>>(nullptr, W3, nullptr);
    k_spmm<128, true, 3, 2><<<SP, 128>>>(b3);

    k_pool<<<(NN + 63) / 64, 128>>>(batch);
    k_cls <<<NG, 128>>>(Wc1, bc1, Wc2, bc2, out);
}

// round 15
// speedup vs baseline: 1.3735x; 1.0934x over previous
#include <cuda_runtime.h>
#include <cuda_bf16.h>
#include <cuda_fp16.h>
#include <math.h>
#include <stdint.h>

// ---------------------------------------------------------------------------
// GCN_Protein: 3x GCNConv -> mean pool -> MLP -> log_softmax
//   R14: SpMM is LTS-bound (1.74 GB of L2 gathers) -> fp16 feature gathers.
//        Producers write fp16 directly (GEMM1/GEMM3 epilogue, SpMM1 output);
//        fp32 accumulation + fp32 edge weights retained. GEMM-input and
//        pool-input tensors stay fp32.
//   GEMM pipeline (R13) / CSR build / pool / cls unchanged.
// ---------------------------------------------------------------------------

#define NN 100000
#define NE 1600000
#define NTOT (NN + NE)
#define NG 512
#define OUTF 10

#define SCAN_B 512
#define SCAN_NB ((NN + SCAN_B - 1) / SCAN_B)   // 196

// ------------------------- scratch (device globals) ------------------------
__device__ int   g_e64;
__device__ int   g_b64;
__device__ int   g_deg[NN];
__device__ int   g_rowptr[NN + 1];
__device__ int   g_cursor[NN];
__device__ float g_dinv[NN];
__device__ int   g_part[SCAN_NB];
__device__ int   g_partoff[SCAN_NB];
__device__ int2  g_colw[NTOT];               // packed {col, float_as_int(wgt)}
__device__ float g_bufA[(size_t)NN * 64];
__device__ float g_bufB[(size_t)NN * 64];
__device__ float g_bufC[(size_t)NN * 128];
__device__ float g_bufD[(size_t)NN * 128];
__device__ float g_pool[NG * 128];
__device__ float g_cnt[NG];

template <int ID>
__device__ __forceinline__ float* scratch() {
    if (ID == 0) return g_bufA;
    if (ID == 1) return g_bufB;
    if (ID == 2) return g_bufC;
    return g_bufD;
}

__device__ __forceinline__ int clampi(int v, int hi) {
    return v < 0 ? 0 : (v >= hi ? hi - 1 : v);
}

__device__ __forceinline__ int load_idx(const int* __restrict__ p, int i, int is64) {
    return is64 ? p[2 * i] : p[i];
}

// ------------------------------ mma helpers ---------------------------------
__device__ __forceinline__ void mma_16816(float* c, const uint32_t* a,
                                          uint32_t b0, uint32_t b1) {
    asm volatile(
        "mma.sync.aligned.m16n8k16.row.col.f32.bf16.bf16.f32 "
        "{%0,%1,%2,%3}, {%4,%5,%6,%7}, {%8,%9}, {%0,%1,%2,%3};"
        : "+f"(c[0]), "+f"(c[1]), "+f"(c[2]), "+f"(c[3])
        : "r"(a[0]), "r"(a[1]), "r"(a[2]), "r"(a[3]), "r"(b0), "r"(b1));
}

__device__ __forceinline__ void ldmx4(uint32_t* r, uint32_t addr) {
    asm volatile(
        "ldmatrix.sync.aligned.m8n8.x4.shared.b16 {%0,%1,%2,%3}, [%4];"
        : "=r"(r[0]), "=r"(r[1]), "=r"(r[2]), "=r"(r[3]) : "r"(addr));
}

__device__ __forceinline__ uint32_t smem_u32(const void* p) {
    return (uint32_t)__cvta_generic_to_shared(p);
}

__device__ __forceinline__ uint32_t pk(__nv_bfloat16 a, __nv_bfloat16 b) {
    return (uint32_t)__bfloat16_as_ushort(a) | ((uint32_t)__bfloat16_as_ushort(b) << 16);
}

__device__ __forceinline__ void split2(float x, float y, uint32_t& hh, uint32_t& ll) {
    __nv_bfloat16 h0 = __float2bfloat16(x);
    __nv_bfloat16 l0 = __float2bfloat16(x - __bfloat162float(h0));
    __nv_bfloat16 h1 = __float2bfloat16(y);
    __nv_bfloat16 l1 = __float2bfloat16(y - __bfloat162float(h1));
    hh = pk(h0, h1);
    ll = pk(l0, l1);
}

// ------------------------------ dtype detection ------------------------------
__global__ void k_detect(const int* __restrict__ ei, const int* __restrict__ batch) {
    __shared__ int nz_e, nz_b;
    int t = threadIdx.x;                       // 128 threads
    if (t == 0) { nz_e = 0; nz_b = 0; }
    __syncthreads();
    long long stride = (2LL * NE) / 128;
    int we = (int)((long long)t * stride) | 1;
    if (ei[we] != 0) atomicAdd(&nz_e, 1);
    int wb = (NN - 1 - 2 * t) | 1;
    if (batch[wb] != 0) atomicAdd(&nz_b, 1);
    __syncthreads();
    if (t == 0) { g_e64 = (nz_e == 0); g_b64 = (nz_b == 0); }
}

// ------------------------------ preprocessing ------------------------------
__global__ void k_init() {
    int i = blockIdx.x * blockDim.x + threadIdx.x;
    if (i < NN) { g_deg[i] = 1; g_cursor[i] = 0; }   // self-loop contributes 1
    if (i < NG * 128) g_pool[i] = 0.f;
    if (i < NG) g_cnt[i] = 0.f;
}

__global__ void k_count(const int* __restrict__ ei) {
    int e = blockIdx.x * blockDim.x + threadIdx.x;
    if (e < NE) {
        int d = clampi(load_idx(ei, NE + e, g_e64), NN);
        atomicAdd(&g_deg[d], 1);
    }
}

__global__ void k_part() {
    __shared__ int red[SCAN_B];
    int t = threadIdx.x;
    int i = blockIdx.x * SCAN_B + t;
    red[t] = (i < NN) ? g_deg[i] : 0;
    __syncthreads();
#pragma unroll
    for (int off = SCAN_B / 2; off > 0; off >>= 1) {
        if (t < off) red[t] += red[t + off];
        __syncthreads();
    }
    if (t == 0) g_part[blockIdx.x] = red[0];
}

__global__ void k_scanpart() {
    __shared__ int s[256];
    int t = threadIdx.x;
    int v = (t < SCAN_NB) ? g_part[t] : 0;
    s[t] = v;
    __syncthreads();
#pragma unroll
    for (int off = 1; off < 256; off <<= 1) {
        int x = (t >= off) ? s[t - off] : 0;
        __syncthreads();
        s[t] += x;
        __syncthreads();
    }
    if (t < SCAN_NB) g_partoff[t] = s[t] - v;  // exclusive
}

__global__ void k_write() {
    __shared__ int s[SCAN_B];
    int t = threadIdx.x;
    int i = blockIdx.x * SCAN_B + t;
    int v = (i < NN) ? g_deg[i] : 0;
    s[t] = v;
    __syncthreads();
#pragma unroll
    for (int off = 1; off < SCAN_B; off <<= 1) {
        int x = (t >= off) ? s[t - off] : 0;
        __syncthreads();
        s[t] += x;
        __syncthreads();
    }
    int base = g_partoff[blockIdx.x];
    if (i < NN) {
        g_rowptr[i] = base + s[t] - v;         // exclusive
        g_dinv[i]   = rsqrtf((float)v);
    }
    if (i == NN - 1) g_rowptr[NN] = base + s[t];
}

__global__ void k_fill(const int* __restrict__ ei) {
    int idx = blockIdx.x * blockDim.x + threadIdx.x;
    if (idx < NN) {
        int pos = g_rowptr[idx] + atomicAdd(&g_cursor[idx], 1);
        float di = g_dinv[idx];
        g_colw[pos] = make_int2(idx, __float_as_int(di * di));
    } else if (idx < NTOT) {
        int e = idx - NN;
        int is64 = g_e64;
        int s = clampi(load_idx(ei, e, is64), NN);
        int d = clampi(load_idx(ei, NE + e, is64), NN);
        int pos = g_rowptr[d] + atomicAdd(&g_cursor[d], 1);
        g_colw[pos] = make_int2(s, __float_as_int(g_dinv[s] * g_dinv[d]));
    }
}

// ---------------------------------- SpMM -----------------------------------
// warp-per-node; INH/OUTH select fp16 feature layout (gather traffic /2).
// fp32 accumulation and fp32 edge weights always.
template <int F, bool EPI, int IN, int OUT, bool INH, bool OUTH>
__global__ void k_spmm(const float* __restrict__ bias) {
    const void* hinv  = scratch<IN>();
    void*       houtv = scratch<OUT>();
    constexpr int VEC = F / 32;          // features per lane (2 or 4)
    int warp = (blockIdx.x * blockDim.x + threadIdx.x) >> 5;
    int lane = threadIdx.x & 31;
    if (warp >= NN) return;
    int beg = g_rowptr[warp], end = g_rowptr[warp + 1];
    int f0 = lane * VEC;
    float acc[VEC];
#pragma unroll
    for (int v = 0; v < VEC; v++) acc[v] = 0.f;

    auto gather = [&](int2 e) {
        float wt = __int_as_float(e.y);
        if (INH) {
            const __half* hp = (const __half*)hinv + (size_t)e.x * F + f0;
            if (VEC == 4) {
                uint2 u = *(const uint2*)hp;
                float2 p0 = __half22float2(*(const __half2*)&u.x);
                float2 p1 = __half22float2(*(const __half2*)&u.y);
                acc[0] += wt * p0.x; acc[1] += wt * p0.y;
                acc[2] += wt * p1.x; acc[3] += wt * p1.y;
            } else {
                float2 p0 = __half22float2(*(const __half2*)hp);
                acc[0] += wt * p0.x; acc[1] += wt * p0.y;
            }
        } else {
            const float* fp = (const float*)hinv + (size_t)e.x * F + f0;
            if (VEC == 4) {
                float4 v = *(const float4*)fp;
                acc[0] += wt * v.x; acc[1] += wt * v.y;
                acc[2] += wt * v.z; acc[3] += wt * v.w;
            } else {
                float2 v = *(const float2*)fp;
                acc[0] += wt * v.x; acc[1] += wt * v.y;
            }
        }
    };

    int k = beg;
    for (; k + 2 <= end; k += 2) {
        int2 e0 = g_colw[k];
        int2 e1 = g_colw[k + 1];
        gather(e0);
        gather(e1);
    }
    if (k < end) gather(g_colw[k]);

    if (EPI) {
#pragma unroll
        for (int v = 0; v < VEC; v++) {
            acc[v] += bias[f0 + v];
            acc[v] = fmaxf(acc[v], 0.f);
        }
    }
    if (OUTH) {
        __half* qp = (__half*)houtv + (size_t)warp * F + f0;
        if (VEC == 4) {
            uint2 u;
            *(__half2*)&u.x = __float22half2_rn(make_float2(acc[0], acc[1]));
            *(__half2*)&u.y = __float22half2_rn(make_float2(acc[2], acc[3]));
            *(uint2*)qp = u;
        } else {
            *(__half2*)qp = __float22half2_rn(make_float2(acc[0], acc[1]));
        }
    } else {
        float* qp = (float*)houtv + (size_t)warp * F + f0;
        if (VEC == 4) *(float4*)qp = make_float4(acc[0], acc[1], acc[2], acc[3]);
        else          *(float2*)qp = make_float2(acc[0], acc[1]);
    }
}

// ----------------------- mma.sync split-bf16 GEMM ---------------------------
// C[N, BN] = A[N, K] @ W[K, BN] (+bias, relu). Block: 128 rows x 64 cols.
// Smem [hi|lo] segments, 3 passes (Ahi*Bhi + Ahi*Blo + Alo*Bhi), double-
// buffered software pipeline. OUTH: epilogue stores fp16 (for SpMM consumers).
template <int K, int BN, bool EPI, int IN, int OUT, bool OUTH>
__global__ __launch_bounds__(256, 2)
void k_gemm_mma(const float* __restrict__ Aext, const float* __restrict__ W,
                const float* __restrict__ bias) {
    constexpr int BM = 128, BNT = 64;
    constexpr int KC = 16;               // original k per chunk
    constexpr int NCH = K / KC;
    constexpr int LD = 2 * KC + 8;       // 40 halves

    const float* __restrict__ A = (IN < 0) ? Aext : scratch<(IN < 0) ? 0 : IN>();
    void* Cv = scratch<OUT>();

    __shared__ __align__(16) __nv_bfloat16 As[2][BM][LD];
    __shared__ __align__(16) __nv_bfloat16 Bs[2][BNT][LD];

    int tid = threadIdx.x;
    int wid = tid >> 5;
    int lane = tid & 31;
    int g = lane >> 2;
    int tq = lane & 3;
    int row0 = blockIdx.x * BM;
    int n0 = blockIdx.y * BNT;

    int mat = lane >> 3;
    int mrow = lane & 7;
    int a_roff = ((mat & 1) << 3) + mrow;
    int a_coff = (mat >> 1) << 3;
    int b_roff = ((mat >> 1) << 3) + mrow;
    int b_coff = (mat & 1) << 3;

    int am[4], ak[4];
#pragma unroll
    for (int j = 0; j < 4; j++) {
        int i = tid + 256 * j;
        am[j] = i >> 3;
        ak[j] = (i & 7) * 2;
    }
    int bn[2], bk[2];
#pragma unroll
    for (int j = 0; j < 2; j++) {
        int i = tid + 256 * j;
        bn[j] = i & 63;
        bk[j] = (i >> 6) * 2;
    }

    float2 aR[4];
    float  bR[2][2];

    auto ldg_chunk = [&](int ch) {
#pragma unroll
        for (int j = 0; j < 4; j++) {
            int r = row0 + am[j];
            aR[j] = (r < NN) ? *(const float2*)(A + (size_t)r * K + ch * KC + ak[j])
                             : make_float2(0.f, 0.f);
        }
#pragma unroll
        for (int j = 0; j < 2; j++) {
            bR[j][0] = W[(size_t)(ch * KC + bk[j]) * BN + n0 + bn[j]];
            bR[j][1] = W[(size_t)(ch * KC + bk[j] + 1) * BN + n0 + bn[j]];
        }
    };

    auto cvt_chunk = [&](int buf) {
#pragma unroll
        for (int j = 0; j < 4; j++) {
            uint32_t hh, ll;
            split2(aR[j].x, aR[j].y, hh, ll);
            *(uint32_t*)&As[buf][am[j]][ak[j]] = hh;
            *(uint32_t*)&As[buf][am[j]][KC + ak[j]] = ll;
        }
#pragma unroll
        for (int j = 0; j < 2; j++) {
            uint32_t hh, ll;
            split2(bR[j][0], bR[j][1], hh, ll);
            *(uint32_t*)&Bs[buf][bn[j]][bk[j]] = hh;
            *(uint32_t*)&Bs[buf][bn[j]][KC + bk[j]] = ll;
        }
    };

    float acc[8][4];
#pragma unroll
    for (int i = 0; i < 8; i++)
#pragma unroll
        for (int j = 0; j < 4; j++) acc[i][j] = 0.f;

    ldg_chunk(0);
    cvt_chunk(0);
    __syncthreads();

    int m0 = wid * 16;
    for (int ch = 0; ch < NCH; ch++) {
        int buf = ch & 1;
        if (ch + 1 < NCH) ldg_chunk(ch + 1);

        uint32_t aH[4], aL[4];
        ldmx4(aH, smem_u32(&As[buf][m0 + a_roff][a_coff]));
        ldmx4(aL, smem_u32(&As[buf][m0 + a_roff][KC + a_coff]));
#pragma unroll
        for (int ntp = 0; ntp < 4; ntp++) {
            uint32_t bH[4], bL[4];
            ldmx4(bH, smem_u32(&Bs[buf][ntp * 16 + b_roff][b_coff]));
            ldmx4(bL, smem_u32(&Bs[buf][ntp * 16 + b_roff][KC + b_coff]));
            mma_16816(acc[2 * ntp + 0], aH, bH[0], bH[1]);
            mma_16816(acc[2 * ntp + 1], aH, bH[2], bH[3]);
            mma_16816(acc[2 * ntp + 0], aH, bL[0], bL[1]);
            mma_16816(acc[2 * ntp + 1], aH, bL[2], bL[3]);
            mma_16816(acc[2 * ntp + 0], aL, bH[0], bH[1]);
            mma_16816(acc[2 * ntp + 1], aL, bH[2], bH[3]);
        }

        if (ch + 1 < NCH) cvt_chunk(1 - buf);
        __syncthreads();
    }

    // --- epilogue ---
    int r_lo = row0 + wid * 16 + g;
    int r_hi = r_lo + 8;
#pragma unroll
    for (int nt = 0; nt < 8; nt++) {
        int col = nt * 8 + tq * 2;
        float2 v0 = make_float2(acc[nt][0], acc[nt][1]);
        float2 v1 = make_float2(acc[nt][2], acc[nt][3]);
        if (EPI) {
            float bA = bias[n0 + col], bB = bias[n0 + col + 1];
            v0.x = fmaxf(v0.x + bA, 0.f); v0.y = fmaxf(v0.y + bB, 0.f);
            v1.x = fmaxf(v1.x + bA, 0.f); v1.y = fmaxf(v1.y + bB, 0.f);
        }
        if (OUTH) {
            __half* Ch = (__half*)Cv;
            if (r_lo < NN)
                *(__half2*)(Ch + (size_t)r_lo * BN + n0 + col) = __float22half2_rn(v0);
            if (r_hi < NN)
                *(__half2*)(Ch + (size_t)r_hi * BN + n0 + col) = __float22half2_rn(v1);
        } else {
            float* C = (float*)Cv;
            if (r_lo < NN) *(float2*)(C + (size_t)r_lo * BN + n0 + col) = v0;
            if (r_hi < NN) *(float2*)(C + (size_t)r_hi * BN + n0 + col) = v1;
        }
    }
}

// ------------------------------- mean pooling -------------------------------
__global__ void k_pool(const int* __restrict__ batch) {
    const float* __restrict__ h = g_bufC;
    constexpr int CH = 64;
    int n0 = blockIdx.x * CH;
    int t  = threadIdx.x;                 // 128 = feature
    if (n0 >= NN) return;
    int is64 = g_b64;
    int end = n0 + CH; if (end > NN) end = NN;
    float acc = 0.f, cacc = 0.f;
    int cur = clampi(load_idx(batch, n0, is64), NG);
    for (int n = n0; n < end; n++) {
        int g = clampi(load_idx(batch, n, is64), NG);
        if (g != cur) {
            atomicAdd(&g_pool[cur * 128 + t], acc);
            if (t == 0) atomicAdd(&g_cnt[cur], cacc);
            acc = 0.f; cacc = 0.f; cur = g;
        }
        acc  += h[(size_t)n * 128 + t];
        cacc += 1.f;
    }
    atomicAdd(&g_pool[cur * 128 + t], acc);
    if (t == 0) atomicAdd(&g_cnt[cur], cacc);
}

// --------------------------- classifier + log_softmax -----------------------
__global__ void k_cls(const float* __restrict__ Wc1, const float* __restrict__ bc1,
                      const float* __restrict__ Wc2, const float* __restrict__ bc2,
                      float* __restrict__ out) {
    int g = blockIdx.x;
    int t = threadIdx.x;                  // 128
    __shared__ float p[128];
    __shared__ float z[64];
    __shared__ float lo[OUTF];
    float c = fmaxf(g_cnt[g], 1.f);
    p[t] = g_pool[g * 128 + t] / c;
    __syncthreads();
    if (t < 64) {
        float a = bc1[t];
#pragma unroll 8
        for (int k = 0; k < 128; k++) a += p[k] * Wc1[k * 64 + t];
        z[t] = fmaxf(a, 0.f);
    }
    __syncthreads();
    if (t < OUTF) {
        float a = bc2[t];
#pragma unroll 8
        for (int k = 0; k < 64; k++) a += z[k] * Wc2[k * OUTF + t];
        lo[t] = a;
    }
    __syncthreads();
    if (t < OUTF) {
        float m = lo[0];
#pragma unroll
        for (int i = 1; i < OUTF; i++) m = fmaxf(m, lo[i]);
        float s = 0.f;
#pragma unroll
        for (int i = 0; i < OUTF; i++) s += expf(lo[i] - m);
        out[g * OUTF + t] = lo[t] - m - logf(s);
    }
}

// --------------------------------- launch -----------------------------------
extern "C" void kernel_launch(void* const* d_in, const int* in_sizes, int n_in,
                              void* d_out, int out_size) {
    const float* x     = (const float*)d_in[0];
    const int*   ei    = (const int*)d_in[1];
    const int*   batch = (const int*)d_in[2];
    const float* W1  = (const float*)d_in[3];
    const float* b1  = (const float*)d_in[4];
    const float* W2  = (const float*)d_in[5];
    const float* b2  = (const float*)d_in[6];
    const float* W3  = (const float*)d_in[7];
    const float* b3  = (const float*)d_in[8];
    const float* Wc1 = (const float*)d_in[9];
    const float* bc1 = (const float*)d_in[10];
    const float* Wc2 = (const float*)d_in[11];
    const float* bc2 = (const float*)d_in[12];
    float* out = (float*)d_out;

    const int GBM = (NN + 127) / 128;       // gemm tile rows (782)
    const int SP  = (NN + 3) / 4;           // spmm blocks (4 warps/block)

    k_detect  <<<1, 128>>>(ei, batch);
    k_init    <<<(NN + 255) / 256, 256>>>();
    k_count   <<<(NE + 255) / 256, 256>>>(ei);
    // GEMM1 has no CSR dependency; launch slot 3 = ncu capture slot
    k_gemm_mma<128, 64, false, -1, 0, true><<<dim3(GBM, 1), 256>>>(x, W1, nullptr);
    k_part    <<<SCAN_NB, SCAN_B>>>();
    k_scanpart<<<1, 256>>>();
    k_write   <<<SCAN_NB, SCAN_B>>>();
    k_fill    <<<(NTOT + 255) / 256, 256>>>(ei);

    // buffers: 0=A 1=B 2=C 3=D   (half-typed where noted)
    // L1: t0 = x @ W1 -> A(h16) ; h1 = relu(CSR·A + b1) -> B(h16)
    k_spmm<64, true, 0, 1, true, true><<<SP, 128>>>(b1);
    // L2: s2 = CSR·B -> A(f32) ; h2 = relu(A @ W2 + b2) -> C(f32)
    k_spmm<64, false, 1, 0, true, false><<<SP, 128>>>(nullptr);
    k_gemm_mma<64, 128, true, 0, 2, false><<<dim3(GBM, 2), 256>>>(nullptr, W2, b2);
    // L3: t3 = C @ W3 -> D(h16) ; h3 = relu(CSR·D + b3) -> C(f32)
    k_gemm_mma<128, 128, false, 2, 3, true><<<dim3(GBM, 2), 256>>>(nullptr, W3, nullptr);
    k_spmm<128, true, 3, 2, true, false><<<SP, 128>>>(b3);

    k_pool<<<(NN + 63) / 64, 128>>>(batch);
    k_cls <<<NG, 128>>>(Wc1, bc1, Wc2, bc2, out);
}

// round 16
// speedup vs baseline: 1.5595x; 1.1354x over previous
#include <cuda_runtime.h>
#include <cuda_bf16.h>
#include <cuda_fp16.h>
#include <math.h>
#include <stdint.h>

// ---------------------------------------------------------------------------
// GCN_Protein: 3x GCNConv -> mean pool -> MLP -> log_softmax
//   R15: all-fp16 feature datapath + single-pass fp16 HMMA GEMM.
//        fp16 products are exact in fp32 accum -> no split needed; only
//        weight rounding (~6e-5 RMS) enters. 3x fewer MMAs, 2x fewer
//        ldmatrix, half smem, 3 CTAs/SM. SpMM gathers/writes all fp16.
//   CSR build / cls unchanged; pool reads fp16.
// ---------------------------------------------------------------------------

#define NN 100000
#define NE 1600000
#define NTOT (NN + NE)
#define NG 512
#define OUTF 10

#define SCAN_B 512
#define SCAN_NB ((NN + SCAN_B - 1) / SCAN_B)   // 196

// ------------------------- scratch (device globals) ------------------------
__device__ int   g_e64;
__device__ int   g_b64;
__device__ int   g_deg[NN];
__device__ int   g_rowptr[NN + 1];
__device__ int   g_cursor[NN];
__device__ float g_dinv[NN];
__device__ int   g_part[SCAN_NB];
__device__ int   g_partoff[SCAN_NB];
__device__ int2  g_colw[NTOT];               // packed {col, float_as_int(wgt)}
__device__ float g_bufA[(size_t)NN * 64];
__device__ float g_bufB[(size_t)NN * 64];
__device__ float g_bufC[(size_t)NN * 128];
__device__ float g_bufD[(size_t)NN * 128];
__device__ float g_pool[NG * 128];
__device__ float g_cnt[NG];

template <int ID>
__device__ __forceinline__ float* scratch() {
    if (ID == 0) return g_bufA;
    if (ID == 1) return g_bufB;
    if (ID == 2) return g_bufC;
    return g_bufD;
}

__device__ __forceinline__ int clampi(int v, int hi) {
    return v < 0 ? 0 : (v >= hi ? hi - 1 : v);
}

__device__ __forceinline__ int load_idx(const int* __restrict__ p, int i, int is64) {
    return is64 ? p[2 * i] : p[i];
}

// ------------------------------ mma helpers ---------------------------------
__device__ __forceinline__ void mma_f16(float* c, const uint32_t* a,
                                        uint32_t b0, uint32_t b1) {
    asm volatile(
        "mma.sync.aligned.m16n8k16.row.col.f32.f16.f16.f32 "
        "{%0,%1,%2,%3}, {%4,%5,%6,%7}, {%8,%9}, {%0,%1,%2,%3};"
        : "+f"(c[0]), "+f"(c[1]), "+f"(c[2]), "+f"(c[3])
        : "r"(a[0]), "r"(a[1]), "r"(a[2]), "r"(a[3]), "r"(b0), "r"(b1));
}

__device__ __forceinline__ void ldmx4(uint32_t* r, uint32_t addr) {
    asm volatile(
        "ldmatrix.sync.aligned.m8n8.x4.shared.b16 {%0,%1,%2,%3}, [%4];"
        : "=r"(r[0]), "=r"(r[1]), "=r"(r[2]), "=r"(r[3]) : "r"(addr));
}

__device__ __forceinline__ uint32_t smem_u32(const void* p) {
    return (uint32_t)__cvta_generic_to_shared(p);
}

__device__ __forceinline__ uint32_t pkh(float x, float y) {
    __half2 h = __float22half2_rn(make_float2(x, y));
    return *(uint32_t*)&h;
}

// ------------------------------ dtype detection ------------------------------
__global__ void k_detect(const int* __restrict__ ei, const int* __restrict__ batch) {
    __shared__ int nz_e, nz_b;
    int t = threadIdx.x;                       // 128 threads
    if (t == 0) { nz_e = 0; nz_b = 0; }
    __syncthreads();
    long long stride = (2LL * NE) / 128;
    int we = (int)((long long)t * stride) | 1;
    if (ei[we] != 0) atomicAdd(&nz_e, 1);
    int wb = (NN - 1 - 2 * t) | 1;
    if (batch[wb] != 0) atomicAdd(&nz_b, 1);
    __syncthreads();
    if (t == 0) { g_e64 = (nz_e == 0); g_b64 = (nz_b == 0); }
}

// ------------------------------ preprocessing ------------------------------
__global__ void k_init() {
    int i = blockIdx.x * blockDim.x + threadIdx.x;
    if (i < NN) { g_deg[i] = 1; g_cursor[i] = 0; }   // self-loop contributes 1
    if (i < NG * 128) g_pool[i] = 0.f;
    if (i < NG) g_cnt[i] = 0.f;
}

__global__ void k_count(const int* __restrict__ ei) {
    int e = blockIdx.x * blockDim.x + threadIdx.x;
    if (e < NE) {
        int d = clampi(load_idx(ei, NE + e, g_e64), NN);
        atomicAdd(&g_deg[d], 1);
    }
}

__global__ void k_part() {
    __shared__ int red[SCAN_B];
    int t = threadIdx.x;
    int i = blockIdx.x * SCAN_B + t;
    red[t] = (i < NN) ? g_deg[i] : 0;
    __syncthreads();
#pragma unroll
    for (int off = SCAN_B / 2; off > 0; off >>= 1) {
        if (t < off) red[t] += red[t + off];
        __syncthreads();
    }
    if (t == 0) g_part[blockIdx.x] = red[0];
}

__global__ void k_scanpart() {
    __shared__ int s[256];
    int t = threadIdx.x;
    int v = (t < SCAN_NB) ? g_part[t] : 0;
    s[t] = v;
    __syncthreads();
#pragma unroll
    for (int off = 1; off < 256; off <<= 1) {
        int x = (t >= off) ? s[t - off] : 0;
        __syncthreads();
        s[t] += x;
        __syncthreads();
    }
    if (t < SCAN_NB) g_partoff[t] = s[t] - v;  // exclusive
}

__global__ void k_write() {
    __shared__ int s[SCAN_B];
    int t = threadIdx.x;
    int i = blockIdx.x * SCAN_B + t;
    int v = (i < NN) ? g_deg[i] : 0;
    s[t] = v;
    __syncthreads();
#pragma unroll
    for (int off = 1; off < SCAN_B; off <<= 1) {
        int x = (t >= off) ? s[t - off] : 0;
        __syncthreads();
        s[t] += x;
        __syncthreads();
    }
    int base = g_partoff[blockIdx.x];
    if (i < NN) {
        g_rowptr[i] = base + s[t] - v;         // exclusive
        g_dinv[i]   = rsqrtf((float)v);
    }
    if (i == NN - 1) g_rowptr[NN] = base + s[t];
}

__global__ void k_fill(const int* __restrict__ ei) {
    int idx = blockIdx.x * blockDim.x + threadIdx.x;
    if (idx < NN) {
        int pos = g_rowptr[idx] + atomicAdd(&g_cursor[idx], 1);
        float di = g_dinv[idx];
        g_colw[pos] = make_int2(idx, __float_as_int(di * di));
    } else if (idx < NTOT) {
        int e = idx - NN;
        int is64 = g_e64;
        int s = clampi(load_idx(ei, e, is64), NN);
        int d = clampi(load_idx(ei, NE + e, is64), NN);
        int pos = g_rowptr[d] + atomicAdd(&g_cursor[d], 1);
        g_colw[pos] = make_int2(s, __float_as_int(g_dinv[s] * g_dinv[d]));
    }
}

// ---------------------------------- SpMM -----------------------------------
// warp-per-node; all-fp16 feature layout in/out, fp32 accumulation/weights.
template <int F, bool EPI, int IN, int OUT>
__global__ void k_spmm(const float* __restrict__ bias) {
    const __half* __restrict__ hin = (const __half*)scratch<IN>();
    __half*       __restrict__ hout = (__half*)scratch<OUT>();
    constexpr int VEC = F / 32;          // features per lane (2 or 4)
    int warp = (blockIdx.x * blockDim.x + threadIdx.x) >> 5;
    int lane = threadIdx.x & 31;
    if (warp >= NN) return;
    int beg = g_rowptr[warp], end = g_rowptr[warp + 1];
    int f0 = lane * VEC;
    float acc[VEC];
#pragma unroll
    for (int v = 0; v < VEC; v++) acc[v] = 0.f;

    auto gather = [&](int2 e) {
        float wt = __int_as_float(e.y);
        const __half* hp = hin + (size_t)e.x * F + f0;
        if (VEC == 4) {
            uint2 u = *(const uint2*)hp;
            float2 p0 = __half22float2(*(const __half2*)&u.x);
            float2 p1 = __half22float2(*(const __half2*)&u.y);
            acc[0] += wt * p0.x; acc[1] += wt * p0.y;
            acc[2] += wt * p1.x; acc[3] += wt * p1.y;
        } else {
            float2 p0 = __half22float2(*(const __half2*)hp);
            acc[0] += wt * p0.x; acc[1] += wt * p0.y;
        }
    };

    int k = beg;
    for (; k + 2 <= end; k += 2) {
        int2 e0 = g_colw[k];
        int2 e1 = g_colw[k + 1];
        gather(e0);
        gather(e1);
    }
    if (k < end) gather(g_colw[k]);

    if (EPI) {
#pragma unroll
        for (int v = 0; v < VEC; v++) {
            acc[v] += bias[f0 + v];
            acc[v] = fmaxf(acc[v], 0.f);
        }
    }
    __half* qp = hout + (size_t)warp * F + f0;
    if (VEC == 4) {
        uint2 u;
        *(__half2*)&u.x = __float22half2_rn(make_float2(acc[0], acc[1]));
        *(__half2*)&u.y = __float22half2_rn(make_float2(acc[2], acc[3]));
        *(uint2*)qp = u;
    } else {
        *(__half2*)qp = __float22half2_rn(make_float2(acc[0], acc[1]));
    }
}

// ----------------------- single-pass fp16 HMMA GEMM --------------------------
// C[N, BN] = A[N, K] @ W[K, BN] (+bias, relu). Block: 128 rows x 64 cols
// (blockIdx.y selects 64-col half for BN=128). 256 threads = 8 warps; warp w
// computes rows [w*16,w*16+16) x 64 cols. KC=16 = one k-step per chunk.
// A is fp16 (INH) or fp32 (GEMM1's x); W fp32 -> fp16. Output fp16.
// fp16 inputs make products exact; only W/x rounding (~6e-5) enters.
template <int K, int BN, bool EPI, int IN, int OUT, bool INH>
__global__ __launch_bounds__(256, 3)
void k_gemm_mma(const float* __restrict__ Aext, const float* __restrict__ W,
                const float* __restrict__ bias) {
    constexpr int BM = 128, BNT = 64;
    constexpr int KC = 16;
    constexpr int NCH = K / KC;
    constexpr int LD = KC + 8;           // 24 halves = 48B rows (conflict-free)

    const void* Ain = (IN < 0) ? (const void*)Aext : (const void*)scratch<(IN < 0) ? 0 : IN>();
    __half* Ch = (__half*)scratch<OUT>();

    __shared__ __align__(16) __half As[2][BM][LD];   // 2 x 6144 B
    __shared__ __align__(16) __half Bs[2][BNT][LD];  // 2 x 3072 B

    int tid = threadIdx.x;
    int wid = tid >> 5;
    int lane = tid & 31;
    int g = lane >> 2;
    int tq = lane & 3;
    int row0 = blockIdx.x * BM;
    int n0 = blockIdx.y * BNT;

    int mat = lane >> 3;
    int mrow = lane & 7;
    int a_roff = ((mat & 1) << 3) + mrow;   // mats {0,1}={m,m+8}@k0, {2,3}@k8
    int a_coff = (mat >> 1) << 3;
    int b_roff = ((mat >> 1) << 3) + mrow;  // mats {0,1}=nt0@{k0,k8}, {2,3}=nt1
    int b_coff = (mat & 1) << 3;

    // staging: A = 128x16 = 2048 elems, 8/thread (one row-half each)
    int a_row = tid >> 1;
    int a_seg = (tid & 1) * 8;
    // B = 16x64 = 1024 elems, 4/thread (4 consecutive k, fixed n)
    int b_n = tid & 63;
    int b_k = (tid >> 6) * 4;

    float  aF[8];
    float  bF[4];

    auto ldg_chunk = [&](int ch) {
        int r = row0 + a_row;
        if (INH) {
            if (r < NN) {
                const __half* Ah = (const __half*)Ain + (size_t)r * K + ch * KC + a_seg;
                uint2 u = *(const uint2*)Ah;
                float2 p0 = __half22float2(*(const __half2*)&u.x);
                float2 p1 = __half22float2(*(const __half2*)&u.y);
                const __half* Ah2 = Ah + 4;
                uint2 u2 = *(const uint2*)Ah2;
                float2 p2 = __half22float2(*(const __half2*)&u2.x);
                float2 p3 = __half22float2(*(const __half2*)&u2.y);
                aF[0] = p0.x; aF[1] = p0.y; aF[2] = p1.x; aF[3] = p1.y;
                aF[4] = p2.x; aF[5] = p2.y; aF[6] = p3.x; aF[7] = p3.y;
            } else {
#pragma unroll
                for (int j = 0; j < 8; j++) aF[j] = 0.f;
            }
        } else {
            if (r < NN) {
                const float* Af = (const float*)Ain + (size_t)r * K + ch * KC + a_seg;
                float4 v0 = *(const float4*)Af;
                float4 v1 = *(const float4*)(Af + 4);
                aF[0] = v0.x; aF[1] = v0.y; aF[2] = v0.z; aF[3] = v0.w;
                aF[4] = v1.x; aF[5] = v1.y; aF[6] = v1.z; aF[7] = v1.w;
            } else {
#pragma unroll
                for (int j = 0; j < 8; j++) aF[j] = 0.f;
            }
        }
#pragma unroll
        for (int j = 0; j < 4; j++)
            bF[j] = W[(size_t)(ch * KC + b_k + j) * BN + n0 + b_n];
    };

    auto cvt_chunk = [&](int buf) {
        uint32_t* ap = (uint32_t*)&As[buf][a_row][a_seg];
        ap[0] = pkh(aF[0], aF[1]);
        ap[1] = pkh(aF[2], aF[3]);
        ap[2] = pkh(aF[4], aF[5]);
        ap[3] = pkh(aF[6], aF[7]);
        uint32_t* bp = (uint32_t*)&Bs[buf][b_n][b_k];
        bp[0] = pkh(bF[0], bF[1]);
        bp[1] = pkh(bF[2], bF[3]);
    };

    float acc[8][4];
#pragma unroll
    for (int i = 0; i < 8; i++)
#pragma unroll
        for (int j = 0; j < 4; j++) acc[i][j] = 0.f;

    ldg_chunk(0);
    cvt_chunk(0);
    __syncthreads();

    int m0 = wid * 16;
    for (int ch = 0; ch < NCH; ch++) {
        int buf = ch & 1;
        if (ch + 1 < NCH) ldg_chunk(ch + 1);    // LDGs overlap mma below

        uint32_t a[4];
        ldmx4(a, smem_u32(&As[buf][m0 + a_roff][a_coff]));
#pragma unroll
        for (int ntp = 0; ntp < 4; ntp++) {
            uint32_t b[4];
            ldmx4(b, smem_u32(&Bs[buf][ntp * 16 + b_roff][b_coff]));
            mma_f16(acc[2 * ntp + 0], a, b[0], b[1]);
            mma_f16(acc[2 * ntp + 1], a, b[2], b[3]);
        }

        if (ch + 1 < NCH) cvt_chunk(1 - buf);
        __syncthreads();
    }

    // --- epilogue (fp16 output) ---
    int r_lo = row0 + wid * 16 + g;
    int r_hi = r_lo + 8;
#pragma unroll
    for (int nt = 0; nt < 8; nt++) {
        int col = nt * 8 + tq * 2;
        float2 v0 = make_float2(acc[nt][0], acc[nt][1]);
        float2 v1 = make_float2(acc[nt][2], acc[nt][3]);
        if (EPI) {
            float bA = bias[n0 + col], bB = bias[n0 + col + 1];
            v0.x = fmaxf(v0.x + bA, 0.f); v0.y = fmaxf(v0.y + bB, 0.f);
            v1.x = fmaxf(v1.x + bA, 0.f); v1.y = fmaxf(v1.y + bB, 0.f);
        }
        if (r_lo < NN)
            *(__half2*)(Ch + (size_t)r_lo * BN + n0 + col) = __float22half2_rn(v0);
        if (r_hi < NN)
            *(__half2*)(Ch + (size_t)r_hi * BN + n0 + col) = __float22half2_rn(v1);
    }
}

// ------------------------------- mean pooling -------------------------------
__global__ void k_pool(const int* __restrict__ batch) {
    const __half* __restrict__ h = (const __half*)g_bufC;
    constexpr int CH = 64;
    int n0 = blockIdx.x * CH;
    int t  = threadIdx.x;                 // 128 = feature
    if (n0 >= NN) return;
    int is64 = g_b64;
    int end = n0 + CH; if (end > NN) end = NN;
    float acc = 0.f, cacc = 0.f;
    int cur = clampi(load_idx(batch, n0, is64), NG);
    for (int n = n0; n < end; n++) {
        int g = clampi(load_idx(batch, n, is64), NG);
        if (g != cur) {
            atomicAdd(&g_pool[cur * 128 + t], acc);
            if (t == 0) atomicAdd(&g_cnt[cur], cacc);
            acc = 0.f; cacc = 0.f; cur = g;
        }
        acc  += __half2float(h[(size_t)n * 128 + t]);
        cacc += 1.f;
    }
    atomicAdd(&g_pool[cur * 128 + t], acc);
    if (t == 0) atomicAdd(&g_cnt[cur], cacc);
}

// --------------------------- classifier + log_softmax -----------------------
__global__ void k_cls(const float* __restrict__ Wc1, const float* __restrict__ bc1,
                      const float* __restrict__ Wc2, const float* __restrict__ bc2,
                      float* __restrict__ out) {
    int g = blockIdx.x;
    int t = threadIdx.x;                  // 128
    __shared__ float p[128];
    __shared__ float z[64];
    __shared__ float lo[OUTF];
    float c = fmaxf(g_cnt[g], 1.f);
    p[t] = g_pool[g * 128 + t] / c;
    __syncthreads();
    if (t < 64) {
        float a = bc1[t];
#pragma unroll 8
        for (int k = 0; k < 128; k++) a += p[k] * Wc1[k * 64 + t];
        z[t] = fmaxf(a, 0.f);
    }
    __syncthreads();
    if (t < OUTF) {
        float a = bc2[t];
#pragma unroll 8
        for (int k = 0; k < 64; k++) a += z[k] * Wc2[k * OUTF + t];
        lo[t] = a;
    }
    __syncthreads();
    if (t < OUTF) {
        float m = lo[0];
#pragma unroll
        for (int i = 1; i < OUTF; i++) m = fmaxf(m, lo[i]);
        float s = 0.f;
#pragma unroll
        for (int i = 0; i < OUTF; i++) s += expf(lo[i] - m);
        out[g * OUTF + t] = lo[t] - m - logf(s);
    }
}

// --------------------------------- launch -----------------------------------
extern "C" void kernel_launch(void* const* d_in, const int* in_sizes, int n_in,
                              void* d_out, int out_size) {
    const float* x     = (const float*)d_in[0];
    const int*   ei    = (const int*)d_in[1];
    const int*   batch = (const int*)d_in[2];
    const float* W1  = (const float*)d_in[3];
    const float* b1  = (const float*)d_in[4];
    const float* W2  = (const float*)d_in[5];
    const float* b2  = (const float*)d_in[6];
    const float* W3  = (const float*)d_in[7];
    const float* b3  = (const float*)d_in[8];
    const float* Wc1 = (const float*)d_in[9];
    const float* bc1 = (const float*)d_in[10];
    const float* Wc2 = (const float*)d_in[11];
    const float* bc2 = (const float*)d_in[12];
    float* out = (float*)d_out;

    const int GBM = (NN + 127) / 128;       // gemm tile rows (782)
    const int SP  = (NN + 3) / 4;           // spmm blocks (4 warps/block)

    k_detect  <<<1, 128>>>(ei, batch);
    k_init    <<<(NN + 255) / 256, 256>>>();
    k_count   <<<(NE + 255) / 256, 256>>>(ei);
    // GEMM1 has no CSR dependency; launch slot 3 = ncu capture slot
    k_gemm_mma<128, 64, false, -1, 0, false><<<dim3(GBM, 1), 256>>>(x, W1, nullptr);
    k_part    <<<SCAN_NB, SCAN_B>>>();
    k_scanpart<<<1, 256>>>();
    k_write   <<<SCAN_NB, SCAN_B>>>();
    k_fill    <<<(NTOT + 255) / 256, 256>>>(ei);

    // buffers (all features fp16): 0=A 1=B 2=C 3=D
    // L1: t0 = x @ W1 -> A ; h1 = relu(CSR·A + b1) -> B
    k_spmm<64, true, 0, 1><<<SP, 128>>>(b1);
    // L2: s2 = CSR·B -> A ; h2 = relu(A @ W2 + b2) -> C
    k_spmm<64, false, 1, 0><<<SP, 128>>>(nullptr);
    k_gemm_mma<64, 128, true, 0, 2, true><<<dim3(GBM, 2), 256>>>(nullptr, W2, b2);
    // L3: t3 = C @ W3 -> D ; h3 = relu(CSR·D + b3) -> C
    k_gemm_mma<128, 128, false, 2, 3, true><<<dim3(GBM, 2), 256>>>(nullptr, W3, nullptr);
    k_spmm<128, true, 3, 2><<<SP, 128>>>(b3);

    k_pool<<<(NN + 63) / 64, 128>>>(batch);
    k_cls <<<NG, 128>>>(Wc1, bc1, Wc2, bc2, out);
}

// round 17
// speedup vs baseline: 1.6716x; 1.0719x over previous
#include <cuda_runtime.h>
#include <cuda_bf16.h>
#include <cuda_fp16.h>
#include <math.h>
#include <stdint.h>

// ---------------------------------------------------------------------------
// GCN_Protein: 3x GCNConv -> mean pool -> MLP -> log_softmax
//   R16: - SpMM F=64: 2 nodes/warp, uint2 (4-half) gathers -> half the LSU ops
//        - GEMM2/3: single-pass BNT=128 (A read once, raw fp16 A staging)
//   All-fp16 feature datapath (R15) / CSR build / pool / cls unchanged.
// ---------------------------------------------------------------------------

#define NN 100000
#define NE 1600000
#define NTOT (NN + NE)
#define NG 512
#define OUTF 10

#define SCAN_B 512
#define SCAN_NB ((NN + SCAN_B - 1) / SCAN_B)   // 196

// ------------------------- scratch (device globals) ------------------------
__device__ int   g_e64;
__device__ int   g_b64;
__device__ int   g_deg[NN];
__device__ int   g_rowptr[NN + 1];
__device__ int   g_cursor[NN];
__device__ float g_dinv[NN];
__device__ int   g_part[SCAN_NB];
__device__ int   g_partoff[SCAN_NB];
__device__ int2  g_colw[NTOT];               // packed {col, float_as_int(wgt)}
__device__ float g_bufA[(size_t)NN * 64];
__device__ float g_bufB[(size_t)NN * 64];
__device__ float g_bufC[(size_t)NN * 128];
__device__ float g_bufD[(size_t)NN * 128];
__device__ float g_pool[NG * 128];
__device__ float g_cnt[NG];

template <int ID>
__device__ __forceinline__ float* scratch() {
    if (ID == 0) return g_bufA;
    if (ID == 1) return g_bufB;
    if (ID == 2) return g_bufC;
    return g_bufD;
}

__device__ __forceinline__ int clampi(int v, int hi) {
    return v < 0 ? 0 : (v >= hi ? hi - 1 : v);
}

__device__ __forceinline__ int load_idx(const int* __restrict__ p, int i, int is64) {
    return is64 ? p[2 * i] : p[i];
}

// ------------------------------ mma helpers ---------------------------------
__device__ __forceinline__ void mma_f16(float* c, const uint32_t* a,
                                        uint32_t b0, uint32_t b1) {
    asm volatile(
        "mma.sync.aligned.m16n8k16.row.col.f32.f16.f16.f32 "
        "{%0,%1,%2,%3}, {%4,%5,%6,%7}, {%8,%9}, {%0,%1,%2,%3};"
        : "+f"(c[0]), "+f"(c[1]), "+f"(c[2]), "+f"(c[3])
        : "r"(a[0]), "r"(a[1]), "r"(a[2]), "r"(a[3]), "r"(b0), "r"(b1));
}

__device__ __forceinline__ void ldmx4(uint32_t* r, uint32_t addr) {
    asm volatile(
        "ldmatrix.sync.aligned.m8n8.x4.shared.b16 {%0,%1,%2,%3}, [%4];"
        : "=r"(r[0]), "=r"(r[1]), "=r"(r[2]), "=r"(r[3]) : "r"(addr));
}

__device__ __forceinline__ uint32_t smem_u32(const void* p) {
    return (uint32_t)__cvta_generic_to_shared(p);
}

__device__ __forceinline__ uint32_t pkh(float x, float y) {
    __half2 h = __float22half2_rn(make_float2(x, y));
    return *(uint32_t*)&h;
}

// ------------------------------ dtype detection ------------------------------
__global__ void k_detect(const int* __restrict__ ei, const int* __restrict__ batch) {
    __shared__ int nz_e, nz_b;
    int t = threadIdx.x;                       // 128 threads
    if (t == 0) { nz_e = 0; nz_b = 0; }
    __syncthreads();
    long long stride = (2LL * NE) / 128;
    int we = (int)((long long)t * stride) | 1;
    if (ei[we] != 0) atomicAdd(&nz_e, 1);
    int wb = (NN - 1 - 2 * t) | 1;
    if (batch[wb] != 0) atomicAdd(&nz_b, 1);
    __syncthreads();
    if (t == 0) { g_e64 = (nz_e == 0); g_b64 = (nz_b == 0); }
}

// ------------------------------ preprocessing ------------------------------
__global__ void k_init() {
    int i = blockIdx.x * blockDim.x + threadIdx.x;
    if (i < NN) { g_deg[i] = 1; g_cursor[i] = 0; }   // self-loop contributes 1
    if (i < NG * 128) g_pool[i] = 0.f;
    if (i < NG) g_cnt[i] = 0.f;
}

__global__ void k_count(const int* __restrict__ ei) {
    int e = blockIdx.x * blockDim.x + threadIdx.x;
    if (e < NE) {
        int d = clampi(load_idx(ei, NE + e, g_e64), NN);
        atomicAdd(&g_deg[d], 1);
    }
}

__global__ void k_part() {
    __shared__ int red[SCAN_B];
    int t = threadIdx.x;
    int i = blockIdx.x * SCAN_B + t;
    red[t] = (i < NN) ? g_deg[i] : 0;
    __syncthreads();
#pragma unroll
    for (int off = SCAN_B / 2; off > 0; off >>= 1) {
        if (t < off) red[t] += red[t + off];
        __syncthreads();
    }
    if (t == 0) g_part[blockIdx.x] = red[0];
}

__global__ void k_scanpart() {
    __shared__ int s[256];
    int t = threadIdx.x;
    int v = (t < SCAN_NB) ? g_part[t] : 0;
    s[t] = v;
    __syncthreads();
#pragma unroll
    for (int off = 1; off < 256; off <<= 1) {
        int x = (t >= off) ? s[t - off] : 0;
        __syncthreads();
        s[t] += x;
        __syncthreads();
    }
    if (t < SCAN_NB) g_partoff[t] = s[t] - v;  // exclusive
}

__global__ void k_write() {
    __shared__ int s[SCAN_B];
    int t = threadIdx.x;
    int i = blockIdx.x * SCAN_B + t;
    int v = (i < NN) ? g_deg[i] : 0;
    s[t] = v;
    __syncthreads();
#pragma unroll
    for (int off = 1; off < SCAN_B; off <<= 1) {
        int x = (t >= off) ? s[t - off] : 0;
        __syncthreads();
        s[t] += x;
        __syncthreads();
    }
    int base = g_partoff[blockIdx.x];
    if (i < NN) {
        g_rowptr[i] = base + s[t] - v;         // exclusive
        g_dinv[i]   = rsqrtf((float)v);
    }
    if (i == NN - 1) g_rowptr[NN] = base + s[t];
}

__global__ void k_fill(const int* __restrict__ ei) {
    int idx = blockIdx.x * blockDim.x + threadIdx.x;
    if (idx < NN) {
        int pos = g_rowptr[idx] + atomicAdd(&g_cursor[idx], 1);
        float di = g_dinv[idx];
        g_colw[pos] = make_int2(idx, __float_as_int(di * di));
    } else if (idx < NTOT) {
        int e = idx - NN;
        int is64 = g_e64;
        int s = clampi(load_idx(ei, e, is64), NN);
        int d = clampi(load_idx(ei, NE + e, is64), NN);
        int pos = g_rowptr[d] + atomicAdd(&g_cursor[d], 1);
        g_colw[pos] = make_int2(s, __float_as_int(g_dinv[s] * g_dinv[d]));
    }
}

// ---------------------------------- SpMM -----------------------------------
// All-fp16 features. F=64: 2 nodes/warp (16 lanes/node); F=128: 1 node/warp.
// Each lane handles 4 halves via one uint2 load. fp32 accum + fp32 weights.
template <int F, bool EPI, int IN, int OUT>
__global__ void k_spmm(const float* __restrict__ bias) {
    const __half* __restrict__ hin = (const __half*)scratch<IN>();
    __half*       __restrict__ hout = (__half*)scratch<OUT>();
    constexpr int LPN = F / 4;           // lanes per node: 16 (F=64) / 32 (F=128)
    constexpr int NPW = 32 / LPN;        // nodes per warp: 2 / 1
    constexpr int LSH = (LPN == 16) ? 4 : 5;

    int warp = (blockIdx.x * blockDim.x + threadIdx.x) >> 5;
    int lane = threadIdx.x & 31;
    int node = warp * NPW + (lane >> LSH);
    int ln   = lane & (LPN - 1);
    if (node >= NN) return;
    int beg = g_rowptr[node], end = g_rowptr[node + 1];
    int f0 = ln * 4;
    float acc[4];
#pragma unroll
    for (int v = 0; v < 4; v++) acc[v] = 0.f;

    auto gather = [&](int2 e) {
        float wt = __int_as_float(e.y);
        const __half* hp = hin + (size_t)e.x * F + f0;
        uint2 u = *(const uint2*)hp;
        float2 p0 = __half22float2(*(const __half2*)&u.x);
        float2 p1 = __half22float2(*(const __half2*)&u.y);
        acc[0] += wt * p0.x; acc[1] += wt * p0.y;
        acc[2] += wt * p1.x; acc[3] += wt * p1.y;
    };

    int k = beg;
    for (; k + 2 <= end; k += 2) {
        int2 e0 = g_colw[k];
        int2 e1 = g_colw[k + 1];
        gather(e0);
        gather(e1);
    }
    if (k < end) gather(g_colw[k]);

    if (EPI) {
#pragma unroll
        for (int v = 0; v < 4; v++) {
            acc[v] += bias[f0 + v];
            acc[v] = fmaxf(acc[v], 0.f);
        }
    }
    __half* qp = hout + (size_t)node * F + f0;
    uint2 u;
    *(__half2*)&u.x = __float22half2_rn(make_float2(acc[0], acc[1]));
    *(__half2*)&u.y = __float22half2_rn(make_float2(acc[2], acc[3]));
    *(uint2*)qp = u;
}

// ----------------------- single-pass fp16 HMMA GEMM --------------------------
// C[N, BN] = A[N, K] @ W[K, BN] (+bias, relu). Block: 128 rows x BNT cols
// (BNT = BN: full width, A read once). 256 threads = 8 warps; warp w computes
// rows [w*16,w*16+16) x BNT cols. KC=16 = one k-step per chunk.
// A fp16 (INH: raw uint4 staging) or fp32 (GEMM1's x); W fp32->fp16; C fp16.
template <int K, int BN, bool EPI, int IN, int OUT, bool INH, int BNT>
__global__ __launch_bounds__(256, (BNT == 64) ? 3 : 2)
void k_gemm_mma(const float* __restrict__ Aext, const float* __restrict__ W,
                const float* __restrict__ bias) {
    constexpr int BM = 128;
    constexpr int KC = 16;
    constexpr int NCH = K / KC;
    constexpr int LD = KC + 8;           // 24 halves = 48B rows
    constexpr int NT = BNT / 8;          // n-tiles (8 or 16)
    constexpr int BK = 16 * BNT / 256;   // W elems per thread (4 or 8)

    const void* Ain = (IN < 0) ? (const void*)Aext : (const void*)scratch<(IN < 0) ? 0 : IN>();
    __half* Ch = (__half*)scratch<OUT>();

    __shared__ __align__(16) __half As[2][BM][LD];
    __shared__ __align__(16) __half Bs[2][BNT][LD];

    int tid = threadIdx.x;
    int wid = tid >> 5;
    int lane = tid & 31;
    int g = lane >> 2;
    int tq = lane & 3;
    int row0 = blockIdx.x * BM;
    int n0 = blockIdx.y * BNT;

    int mat = lane >> 3;
    int mrow = lane & 7;
    int a_roff = ((mat & 1) << 3) + mrow;
    int a_coff = (mat >> 1) << 3;
    int b_roff = ((mat >> 1) << 3) + mrow;
    int b_coff = (mat & 1) << 3;

    // staging: A = 128x16 halves, 8/thread
    int a_row = tid >> 1;
    int a_seg = (tid & 1) * 8;
    // B = 16xBNT, BK consecutive k per thread at fixed n
    int b_n = tid % BNT;
    int b_k = (tid / BNT) * BK;

    uint32_t aU[4];                       // raw fp16 staging (INH)
    float    aF[8];                       // fp32 staging (GEMM1)
    float    bF[8];                       // W staging (BK <= 8)

    auto ldg_chunk = [&](int ch) {
        int r = row0 + a_row;
        if (INH) {
            if (r < NN) {
                const uint4 u = *(const uint4*)((const __half*)Ain +
                                                (size_t)r * K + ch * KC + a_seg);
                aU[0] = u.x; aU[1] = u.y; aU[2] = u.z; aU[3] = u.w;
            } else {
                aU[0] = aU[1] = aU[2] = aU[3] = 0u;
            }
        } else {
            if (r < NN) {
                const float* Af = (const float*)Ain + (size_t)r * K + ch * KC + a_seg;
                float4 v0 = *(const float4*)Af;
                float4 v1 = *(const float4*)(Af + 4);
                aF[0] = v0.x; aF[1] = v0.y; aF[2] = v0.z; aF[3] = v0.w;
                aF[4] = v1.x; aF[5] = v1.y; aF[6] = v1.z; aF[7] = v1.w;
            } else {
#pragma unroll
                for (int j = 0; j < 8; j++) aF[j] = 0.f;
            }
        }
#pragma unroll
        for (int j = 0; j < BK; j++)
            bF[j] = W[(size_t)(ch * KC + b_k + j) * BN + n0 + b_n];
    };

    auto cvt_chunk = [&](int buf) {
        uint32_t* ap = (uint32_t*)&As[buf][a_row][a_seg];
        if (INH) {
            ap[0] = aU[0]; ap[1] = aU[1]; ap[2] = aU[2]; ap[3] = aU[3];
        } else {
            ap[0] = pkh(aF[0], aF[1]);
            ap[1] = pkh(aF[2], aF[3]);
            ap[2] = pkh(aF[4], aF[5]);
            ap[3] = pkh(aF[6], aF[7]);
        }
        uint32_t* bp = (uint32_t*)&Bs[buf][b_n][b_k];
#pragma unroll
        for (int j = 0; j < BK / 2; j++)
            bp[j] = pkh(bF[2 * j], bF[2 * j + 1]);
    };

    float acc[NT][4];
#pragma unroll
    for (int i = 0; i < NT; i++)
#pragma unroll
        for (int j = 0; j < 4; j++) acc[i][j] = 0.f;

    ldg_chunk(0);
    cvt_chunk(0);
    __syncthreads();

    int m0 = wid * 16;
    for (int ch = 0; ch < NCH; ch++) {
        int buf = ch & 1;
        if (ch + 1 < NCH) ldg_chunk(ch + 1);    // LDGs overlap mma below

        uint32_t a[4];
        ldmx4(a, smem_u32(&As[buf][m0 + a_roff][a_coff]));
#pragma unroll
        for (int ntp = 0; ntp < NT / 2; ntp++) {
            uint32_t b[4];
            ldmx4(b, smem_u32(&Bs[buf][ntp * 16 + b_roff][b_coff]));
            mma_f16(acc[2 * ntp + 0], a, b[0], b[1]);
            mma_f16(acc[2 * ntp + 1], a, b[2], b[3]);
        }

        if (ch + 1 < NCH) cvt_chunk(1 - buf);
        __syncthreads();
    }

    // --- epilogue (fp16 output) ---
    int r_lo = row0 + wid * 16 + g;
    int r_hi = r_lo + 8;
#pragma unroll
    for (int nt = 0; nt < NT; nt++) {
        int col = nt * 8 + tq * 2;
        float2 v0 = make_float2(acc[nt][0], acc[nt][1]);
        float2 v1 = make_float2(acc[nt][2], acc[nt][3]);
        if (EPI) {
            float bA = bias[n0 + col], bB = bias[n0 + col + 1];
            v0.x = fmaxf(v0.x + bA, 0.f); v0.y = fmaxf(v0.y + bB, 0.f);
            v1.x = fmaxf(v1.x + bA, 0.f); v1.y = fmaxf(v1.y + bB, 0.f);
        }
        if (r_lo < NN)
            *(__half2*)(Ch + (size_t)r_lo * BN + n0 + col) = __float22half2_rn(v0);
        if (r_hi < NN)
            *(__half2*)(Ch + (size_t)r_hi * BN + n0 + col) = __float22half2_rn(v1);
    }
}

// ------------------------------- mean pooling -------------------------------
__global__ void k_pool(const int* __restrict__ batch) {
    const __half* __restrict__ h = (const __half*)g_bufC;
    constexpr int CH = 64;
    int n0 = blockIdx.x * CH;
    int t  = threadIdx.x;                 // 128 = feature
    if (n0 >= NN) return;
    int is64 = g_b64;
    int end = n0 + CH; if (end > NN) end = NN;
    float acc = 0.f, cacc = 0.f;
    int cur = clampi(load_idx(batch, n0, is64), NG);
    for (int n = n0; n < end; n++) {
        int g = clampi(load_idx(batch, n, is64), NG);
        if (g != cur) {
            atomicAdd(&g_pool[cur * 128 + t], acc);
            if (t == 0) atomicAdd(&g_cnt[cur], cacc);
            acc = 0.f; cacc = 0.f; cur = g;
        }
        acc  += __half2float(h[(size_t)n * 128 + t]);
        cacc += 1.f;
    }
    atomicAdd(&g_pool[cur * 128 + t], acc);
    if (t == 0) atomicAdd(&g_cnt[cur], cacc);
}

// --------------------------- classifier + log_softmax -----------------------
__global__ void k_cls(const float* __restrict__ Wc1, const float* __restrict__ bc1,
                      const float* __restrict__ Wc2, const float* __restrict__ bc2,
                      float* __restrict__ out) {
    int g = blockIdx.x;
    int t = threadIdx.x;                  // 128
    __shared__ float p[128];
    __shared__ float z[64];
    __shared__ float lo[OUTF];
    float c = fmaxf(g_cnt[g], 1.f);
    p[t] = g_pool[g * 128 + t] / c;
    __syncthreads();
    if (t < 64) {
        float a = bc1[t];
#pragma unroll 8
        for (int k = 0; k < 128; k++) a += p[k] * Wc1[k * 64 + t];
        z[t] = fmaxf(a, 0.f);
    }
    __syncthreads();
    if (t < OUTF) {
        float a = bc2[t];
#pragma unroll 8
        for (int k = 0; k < 64; k++) a += z[k] * Wc2[k * OUTF + t];
        lo[t] = a;
    }
    __syncthreads();
    if (t < OUTF) {
        float m = lo[0];
#pragma unroll
        for (int i = 1; i < OUTF; i++) m = fmaxf(m, lo[i]);
        float s = 0.f;
#pragma unroll
        for (int i = 0; i < OUTF; i++) s += expf(lo[i] - m);
        out[g * OUTF + t] = lo[t] - m - logf(s);
    }
}

// --------------------------------- launch -----------------------------------
extern "C" void kernel_launch(void* const* d_in, const int* in_sizes, int n_in,
                              void* d_out, int out_size) {
    const float* x     = (const float*)d_in[0];
    const int*   ei    = (const int*)d_in[1];
    const int*   batch = (const int*)d_in[2];
    const float* W1  = (const float*)d_in[3];
    const float* b1  = (const float*)d_in[4];
    const float* W2  = (const float*)d_in[5];
    const float* b2  = (const float*)d_in[6];
    const float* W3  = (const float*)d_in[7];
    const float* b3  = (const float*)d_in[8];
    const float* Wc1 = (const float*)d_in[9];
    const float* bc1 = (const float*)d_in[10];
    const float* Wc2 = (const float*)d_in[11];
    const float* bc2 = (const float*)d_in[12];
    float* out = (float*)d_out;

    const int GBM  = (NN + 127) / 128;      // gemm tile rows (782)
    const int SP64  = (NN + 7) / 8;         // spmm F=64: 8 nodes/block (4 warps x2)
    const int SP128 = (NN + 3) / 4;         // spmm F=128: 4 nodes/block

    k_detect  <<<1, 128>>>(ei, batch);
    k_init    <<<(NN + 255) / 256, 256>>>();
    k_count   <<<(NE + 255) / 256, 256>>>(ei);
    // GEMM1 has no CSR dependency; launch slot 3 = ncu capture slot
    k_gemm_mma<128, 64, false, -1, 0, false, 64><<<dim3(GBM, 1), 256>>>(x, W1, nullptr);
    k_part    <<<SCAN_NB, SCAN_B>>>();
    k_scanpart<<<1, 256>>>();
    k_write   <<<SCAN_NB, SCAN_B>>>();
    k_fill    <<<(NTOT + 255) / 256, 256>>>(ei);

    // buffers (all features fp16): 0=A 1=B 2=C 3=D
    // L1: t0 = x @ W1 -> A ; h1 = relu(CSR·A + b1) -> B
    k_spmm<64, true, 0, 1><<<SP64, 128>>>(b1);
    // L2: s2 = CSR·B -> A ; h2 = relu(A @ W2 + b2) -> C
    k_spmm<64, false, 1, 0><<<SP64, 128>>>(nullptr);
    k_gemm_mma<64, 128, true, 0, 2, true, 128><<<dim3(GBM, 1), 256>>>(nullptr, W2, b2);
    // L3: t3 = C @ W3 -> D ; h3 = relu(CSR·D + b3) -> C
    k_gemm_mma<128, 128, false, 2, 3, true, 128><<<dim3(GBM, 1), 256>>>(nullptr, W3, nullptr);
    k_spmm<128, true, 3, 2><<<SP128, 128>>>(b3);

    k_pool<<<(NN + 63) / 64, 128>>>(batch);
    k_cls <<<NG, 128>>>(Wc1, bc1, Wc2, bc2, out);
}